// round 2
// baseline (speedup 1.0000x reference)
#include <cuda_runtime.h>

// Problem constants (fixed shapes)
#define NN   20000
#define EE   320000
#define ETOT 340000      // EE + NN self-loops
#define DIN  768
#define F1   1024        // H1*C1
#define H1H  8
#define C1C  128
#define F2   128
#define NEG  0.2f
#define BNEPS 1e-5f

// ---------------- scratch (device globals; no allocation allowed) ----------
__device__ float d_h1[NN * F1];      // x @ W1            (81.9 MB)
__device__ float d_g1[NN * F1];      // GAT1 out -> BN/ELU in place
__device__ float d_h2[NN * F2];      // g1 @ W2
__device__ float d_g2[NN * F2];      // GAT2 out -> BN/ELU in place
__device__ float d_as1[NN * H1H];
__device__ float d_ad1[NN * H1H];
__device__ float d_as2[NN];
__device__ float d_ad2[NN];
__device__ int   d_deg[NN];
__device__ int   d_off[NN + 1];
__device__ int   d_cnt[NN];
__device__ int   d_csr[ETOT];
__device__ float d_bsum[F1];
__device__ float d_bsq[F1];
__device__ float d_scale[F1];
__device__ float d_shift[F1];
__device__ int   d_is64;             // edge_index dtype flag (1 = int64, 0 = int32)

// ---------------- dtype detection ------------------------------------------
// JAX with default x64-disabled config demotes the reference's int64
// edge_index to int32. Detect which layout the harness actually gave us:
// reading an int32 buffer as int64 packs two random indices per word, so
// values are >= 2^32 with overwhelming probability.
__global__ void k_detect(const void* ei) {
    if (threadIdx.x == 0) {
        const long long* p = (const long long*)ei;
        int ok64 = 1;
        for (int i = 0; i < 64; i++) {
            long long v = p[i];
            if (v < 0 || v >= NN) { ok64 = 0; break; }
        }
        d_is64 = ok64;
    }
}

__device__ __forceinline__ int load_idx(const void* ei, int i) {
    int v = d_is64 ? (int)((const long long*)ei)[i] : ((const int*)ei)[i];
    // clamp: turn any surprise into a wrong answer (signal) instead of a crash
    v = v < 0 ? 0 : (v >= NN ? NN - 1 : v);
    return v;
}

// ---------------- CSR build ------------------------------------------------
__global__ void k_count(const void* __restrict__ ei) {
    int i = blockIdx.x * blockDim.x + threadIdx.x;
    if (i >= ETOT) return;
    int dst = (i < EE) ? load_idx(ei, EE + i) : (i - EE);
    atomicAdd(&d_deg[dst], 1);
}

__global__ void k_scan() {   // single block, 1024 threads; scan d_deg -> d_off
    __shared__ int s[1024];
    __shared__ int carry;
    int tid = threadIdx.x;
    if (tid == 0) { carry = 0; d_off[0] = 0; }
    __syncthreads();
    for (int base = 0; base < NN; base += 1024) {
        int i = base + tid;
        int v = (i < NN) ? d_deg[i] : 0;
        s[tid] = v;
        __syncthreads();
        #pragma unroll
        for (int ofs = 1; ofs < 1024; ofs <<= 1) {
            int t = (tid >= ofs) ? s[tid - ofs] : 0;
            __syncthreads();
            s[tid] += t;
            __syncthreads();
        }
        if (i < NN) d_off[i + 1] = carry + s[tid];
        __syncthreads();
        if (tid == 0) carry += s[1023];
        __syncthreads();
    }
}

__global__ void k_scatter(const void* __restrict__ ei) {
    int i = blockIdx.x * blockDim.x + threadIdx.x;
    if (i >= ETOT) return;
    int src, dst;
    if (i < EE) { src = load_idx(ei, i); dst = load_idx(ei, EE + i); }
    else        { src = dst = i - EE; }
    int p = d_off[dst] + atomicAdd(&d_cnt[dst], 1);
    d_csr[p] = src;
}

// ---------------- SGEMM (fp32, 128x128x8, 256 thr, 8x8 microtile) ---------
__global__ __launch_bounds__(256)
void sgemm(const float* __restrict__ A, const float* __restrict__ B,
           float* __restrict__ C, int M, int Nn, int K) {
    __shared__ float As[8][128];
    __shared__ float Bs[8][128];
    int tid = threadIdx.x;
    int blockM = blockIdx.y * 128;
    int blockN = blockIdx.x * 128;
    int tr = tid >> 4, tc = tid & 15;

    int aRow = tid >> 1, aCol = (tid & 1) * 4;
    int bRow = tid >> 5, bCol = (tid & 31) * 4;

    float acc[8][8];
    #pragma unroll
    for (int i = 0; i < 8; i++)
        #pragma unroll
        for (int j = 0; j < 8; j++) acc[i][j] = 0.f;

    for (int k0 = 0; k0 < K; k0 += 8) {
        float4 av = make_float4(0.f, 0.f, 0.f, 0.f);
        int gRow = blockM + aRow;
        if (gRow < M) av = *(const float4*)(A + (size_t)gRow * K + k0 + aCol);
        As[aCol + 0][aRow] = av.x;
        As[aCol + 1][aRow] = av.y;
        As[aCol + 2][aRow] = av.z;
        As[aCol + 3][aRow] = av.w;
        float4 bv = *(const float4*)(B + (size_t)(k0 + bRow) * Nn + blockN + bCol);
        *(float4*)&Bs[bRow][bCol] = bv;
        __syncthreads();
        #pragma unroll
        for (int kk = 0; kk < 8; kk++) {
            float a[8], b[8];
            #pragma unroll
            for (int i = 0; i < 8; i++) a[i] = As[kk][tr * 8 + i];
            #pragma unroll
            for (int j = 0; j < 8; j++) b[j] = Bs[kk][tc * 8 + j];
            #pragma unroll
            for (int i = 0; i < 8; i++)
                #pragma unroll
                for (int j = 0; j < 8; j++) acc[i][j] += a[i] * b[j];
        }
        __syncthreads();
    }
    #pragma unroll
    for (int i = 0; i < 8; i++) {
        int row = blockM + tr * 8 + i;
        if (row < M) {
            float4 v0 = make_float4(acc[i][0], acc[i][1], acc[i][2], acc[i][3]);
            float4 v1 = make_float4(acc[i][4], acc[i][5], acc[i][6], acc[i][7]);
            *(float4*)(C + (size_t)row * Nn + blockN + tc * 8)     = v0;
            *(float4*)(C + (size_t)row * Nn + blockN + tc * 8 + 4) = v1;
        }
    }
}

// ---------------- attention coefficients -----------------------------------
__global__ void k_attn1(const float* __restrict__ atts, const float* __restrict__ attd) {
    int n = blockIdx.x;
    int w = threadIdx.x >> 5, l = threadIdx.x & 31;
    const float* hp = d_h1 + (size_t)n * F1 + w * C1C;
    float ss = 0.f, sd = 0.f;
    for (int c = l; c < C1C; c += 32) {
        float v = hp[c];
        ss += v * atts[w * C1C + c];
        sd += v * attd[w * C1C + c];
    }
    #pragma unroll
    for (int o = 16; o; o >>= 1) {
        ss += __shfl_down_sync(0xffffffffu, ss, o);
        sd += __shfl_down_sync(0xffffffffu, sd, o);
    }
    if (!l) { d_as1[n * H1H + w] = ss; d_ad1[n * H1H + w] = sd; }
}

__global__ void k_attn2(const float* __restrict__ atts, const float* __restrict__ attd) {
    int n = blockIdx.x;
    int l = threadIdx.x;
    const float* hp = d_h2 + (size_t)n * F2;
    float ss = 0.f, sd = 0.f;
    for (int c = l; c < F2; c += 32) {
        float v = hp[c];
        ss += v * atts[c];
        sd += v * attd[c];
    }
    #pragma unroll
    for (int o = 16; o; o >>= 1) {
        ss += __shfl_down_sync(0xffffffffu, ss, o);
        sd += __shfl_down_sync(0xffffffffu, sd, o);
    }
    if (!l) { d_as2[n] = ss; d_ad2[n] = sd; }
}

// ---------------- GAT aggregation (CSR per-dst-node, local softmax) --------
__device__ __forceinline__ void sAtomicMaxF(float* a, float v) {
    int* ai = (int*)a;
    int old = *ai;
    while (__int_as_float(old) < v) {
        int assumed = old;
        old = atomicCAS(ai, assumed, __float_as_int(v));
        if (old == assumed) break;
    }
}

__global__ __launch_bounds__(256)
void k_agg1(const float* __restrict__ bias) {
    int n = blockIdx.x;
    int s0 = d_off[n];
    int deg = d_off[n + 1] - s0;
    __shared__ float sm[H1H], sz[H1H], sad[H1H];
    int tid = threadIdx.x;
    if (tid < H1H) { sad[tid] = d_ad1[n * H1H + tid]; sm[tid] = -1e30f; sz[tid] = 0.f; }
    __syncthreads();
    for (int idx = tid; idx < deg * H1H; idx += 256) {
        int e = idx >> 3, hh = idx & 7;
        int src = d_csr[s0 + e];
        float v = d_as1[src * H1H + hh] + sad[hh];
        v = v > 0.f ? v : NEG * v;
        sAtomicMaxF(&sm[hh], v);
    }
    __syncthreads();
    for (int idx = tid; idx < deg * H1H; idx += 256) {
        int e = idx >> 3, hh = idx & 7;
        int src = d_csr[s0 + e];
        float v = d_as1[src * H1H + hh] + sad[hh];
        v = v > 0.f ? v : NEG * v;
        atomicAdd(&sz[hh], __expf(v - sm[hh]));
    }
    __syncthreads();
    int c0 = tid * 4;
    int hh = c0 >> 7;
    float m = sm[hh], invz = 1.f / sz[hh], ad = sad[hh];
    float4 acc = make_float4(0.f, 0.f, 0.f, 0.f);
    for (int e = 0; e < deg; e++) {
        int src = d_csr[s0 + e];
        float v = d_as1[src * H1H + hh] + ad;
        v = v > 0.f ? v : NEG * v;
        float al = __expf(v - m) * invz;
        float4 hv = *(const float4*)(d_h1 + (size_t)src * F1 + c0);
        acc.x += al * hv.x; acc.y += al * hv.y;
        acc.z += al * hv.z; acc.w += al * hv.w;
    }
    float4 bb = *(const float4*)(bias + c0);
    acc.x += bb.x; acc.y += bb.y; acc.z += bb.z; acc.w += bb.w;
    *(float4*)(d_g1 + (size_t)n * F1 + c0) = acc;
}

__global__ __launch_bounds__(128)
void k_agg2(const float* __restrict__ bias) {
    int n = blockIdx.x;
    int s0 = d_off[n];
    int deg = d_off[n + 1] - s0;
    __shared__ float sm, sz, sad;
    int tid = threadIdx.x;
    if (tid == 0) { sad = d_ad2[n]; sm = -1e30f; sz = 0.f; }
    __syncthreads();
    for (int e = tid; e < deg; e += 128) {
        float v = d_as2[d_csr[s0 + e]] + sad;
        v = v > 0.f ? v : NEG * v;
        sAtomicMaxF(&sm, v);
    }
    __syncthreads();
    for (int e = tid; e < deg; e += 128) {
        float v = d_as2[d_csr[s0 + e]] + sad;
        v = v > 0.f ? v : NEG * v;
        atomicAdd(&sz, __expf(v - sm));
    }
    __syncthreads();
    float m = sm, invz = 1.f / sz, ad = sad;
    float acc = 0.f;
    for (int e = 0; e < deg; e++) {
        int src = d_csr[s0 + e];
        float v = d_as2[src] + ad;
        v = v > 0.f ? v : NEG * v;
        acc += __expf(v - m) * invz * d_h2[(size_t)src * F2 + tid];
    }
    d_g2[(size_t)n * F2 + tid] = acc + bias[tid];
}

// ---------------- BatchNorm + ELU ------------------------------------------
__global__ void bn_stats(const float* __restrict__ x, float* __restrict__ sum,
                         float* __restrict__ sq, int F) {
    int col = blockIdx.x * 128 + threadIdx.x;
    float s = 0.f, q = 0.f;
    for (int r = blockIdx.y; r < NN; r += gridDim.y) {
        float v = x[(size_t)r * F + col];
        s += v; q += v * v;
    }
    atomicAdd(&sum[col], s);
    atomicAdd(&sq[col], q);
}

__global__ void bn_final(const float* __restrict__ sum, const float* __restrict__ sq,
                         const float* __restrict__ gamma, const float* __restrict__ beta,
                         float* __restrict__ scale, float* __restrict__ shift, int F) {
    int c = blockIdx.x * blockDim.x + threadIdx.x;
    if (c < F) {
        float mu  = sum[c] * (1.f / NN);
        float var = sq[c] * (1.f / NN) - mu * mu;
        float sc  = gamma[c] * rsqrtf(var + BNEPS);
        scale[c] = sc;
        shift[c] = beta[c] - mu * sc;
    }
}

__global__ void bn_apply_elu(float* __restrict__ x, const float* __restrict__ scale,
                             const float* __restrict__ shift, int mask, int total) {
    int i = blockIdx.x * blockDim.x + threadIdx.x;
    if (i < total) {
        int c = i & mask;
        float v = x[i] * scale[c] + shift[c];
        x[i] = v > 0.f ? v : (__expf(v) - 1.f);
    }
}

// ---------------- classifier head ------------------------------------------
__global__ __launch_bounds__(64)
void k_classifier(const float* __restrict__ g2, const float* __restrict__ Wc1,
                  const float* __restrict__ bc1, const float* __restrict__ Wc2,
                  const float* __restrict__ bc2, float* __restrict__ out) {
    int n = blockIdx.x;
    int tid = threadIdx.x;
    __shared__ float sx[128], sh[64];
    sx[tid]      = g2[(size_t)n * F2 + tid];
    sx[tid + 64] = g2[(size_t)n * F2 + 64 + tid];
    __syncthreads();
    float s = bc1[tid];
    #pragma unroll 8
    for (int k = 0; k < 128; k++) s += sx[k] * Wc1[k * 64 + tid];
    sh[tid] = fmaxf(s, 0.f);
    __syncthreads();
    if (tid < 2) {
        float o = bc2[tid];
        #pragma unroll 8
        for (int k = 0; k < 64; k++) o += sh[k] * Wc2[k * 2 + tid];
        out[n * 2 + tid] = o;
    }
}

// ---------------- launch ----------------------------------------------------
extern "C" void kernel_launch(void* const* d_in, const int* in_sizes, int n_in,
                              void* d_out, int out_size) {
    const float* x     = (const float*)d_in[0];
    const void*  ei    = d_in[1];                 // int32 or int64 — detected on device
    const float* W1    = (const float*)d_in[2];
    const float* atts1 = (const float*)d_in[3];
    const float* attd1 = (const float*)d_in[4];
    const float* b1    = (const float*)d_in[5];
    const float* W2    = (const float*)d_in[6];
    const float* atts2 = (const float*)d_in[7];
    const float* attd2 = (const float*)d_in[8];
    const float* b2    = (const float*)d_in[9];
    const float* g1    = (const float*)d_in[10];
    const float* be1   = (const float*)d_in[11];
    const float* g2w   = (const float*)d_in[12];
    const float* be2   = (const float*)d_in[13];
    const float* Wc1   = (const float*)d_in[14];
    const float* bc1   = (const float*)d_in[15];
    const float* Wc2   = (const float*)d_in[16];
    const float* bc2   = (const float*)d_in[17];
    float*       out   = (float*)d_out;

    void *p_deg, *p_cnt, *p_h1, *p_g1, *p_h2, *p_g2, *p_bsum, *p_bsq, *p_scale, *p_shift;
    cudaGetSymbolAddress(&p_deg,   d_deg);
    cudaGetSymbolAddress(&p_cnt,   d_cnt);
    cudaGetSymbolAddress(&p_h1,    d_h1);
    cudaGetSymbolAddress(&p_g1,    d_g1);
    cudaGetSymbolAddress(&p_h2,    d_h2);
    cudaGetSymbolAddress(&p_g2,    d_g2);
    cudaGetSymbolAddress(&p_bsum,  d_bsum);
    cudaGetSymbolAddress(&p_bsq,   d_bsq);
    cudaGetSymbolAddress(&p_scale, d_scale);
    cudaGetSymbolAddress(&p_shift, d_shift);

    // CSR build
    cudaMemsetAsync(p_deg, 0, NN * sizeof(int));
    cudaMemsetAsync(p_cnt, 0, NN * sizeof(int));
    k_detect<<<1, 32>>>(ei);
    k_count<<<(ETOT + 255) / 256, 256>>>(ei);
    k_scan<<<1, 1024>>>();
    k_scatter<<<(ETOT + 255) / 256, 256>>>(ei);

    // ---- GAT layer 1 ----
    {
        dim3 grid(F1 / 128, (NN + 127) / 128);
        sgemm<<<grid, 256>>>(x, W1, (float*)p_h1, NN, F1, DIN);
    }
    k_attn1<<<NN, 256>>>(atts1, attd1);
    k_agg1<<<NN, 256>>>(b1);

    // BN1 + ELU (in place on d_g1)
    cudaMemsetAsync(p_bsum, 0, F1 * sizeof(float));
    cudaMemsetAsync(p_bsq,  0, F1 * sizeof(float));
    {
        dim3 grid(F1 / 128, 128);
        bn_stats<<<grid, 128>>>((const float*)p_g1, (float*)p_bsum, (float*)p_bsq, F1);
    }
    bn_final<<<F1 / 128, 128>>>((const float*)p_bsum, (const float*)p_bsq, g1, be1,
                                (float*)p_scale, (float*)p_shift, F1);
    bn_apply_elu<<<(NN * F1 + 255) / 256, 256>>>((float*)p_g1, (const float*)p_scale,
                                                 (const float*)p_shift, F1 - 1, NN * F1);

    // ---- GAT layer 2 ----
    {
        dim3 grid(F2 / 128, (NN + 127) / 128);
        sgemm<<<grid, 256>>>((const float*)p_g1, W2, (float*)p_h2, NN, F2, F1);
    }
    k_attn2<<<NN, 32>>>(atts2, attd2);
    k_agg2<<<NN, 128>>>(b2);

    // BN2 + ELU (in place on d_g2)
    cudaMemsetAsync(p_bsum, 0, F2 * sizeof(float));
    cudaMemsetAsync(p_bsq,  0, F2 * sizeof(float));
    {
        dim3 grid(F2 / 128, 128);
        bn_stats<<<grid, 128>>>((const float*)p_g2, (float*)p_bsum, (float*)p_bsq, F2);
    }
    bn_final<<<1, 128>>>((const float*)p_bsum, (const float*)p_bsq, g2w, be2,
                         (float*)p_scale, (float*)p_shift, F2);
    bn_apply_elu<<<(NN * F2 + 255) / 256, 256>>>((float*)p_g2, (const float*)p_scale,
                                                 (const float*)p_shift, F2 - 1, NN * F2);

    // ---- classifier head ----
    k_classifier<<<NN, 64>>>((const float*)p_g2, Wc1, bc1, Wc2, bc2, out);
}

// round 4
// speedup vs baseline: 1.1410x; 1.1410x over previous
#include <cuda_runtime.h>

// Problem constants (fixed shapes)
#define NN   20000
#define EE   320000
#define ETOT 340000      // EE + NN self-loops
#define DIN  768
#define F1   1024        // H1*C1
#define H1H  8
#define C1C  128
#define F2   128
#define NEG  0.2f
#define BNEPS 1e-5f

// ---------------- scratch (device globals; no allocation allowed) ----------
__device__ float d_h1[NN * F1];      // x @ W1            (81.9 MB)
__device__ float d_g1[NN * F1];      // GAT1 out -> BN/ELU in place
__device__ float d_h2[NN * F2];      // g1 @ W2
__device__ float d_g2[NN * F2];      // GAT2 out -> BN/ELU in place
__device__ float d_as1[NN * H1H];
__device__ float d_ad1[NN * H1H];
__device__ float d_as2[NN];
__device__ float d_ad2[NN];
__device__ int   d_deg[NN];
__device__ int   d_off[NN + 1];
__device__ int   d_cnt[NN];
__device__ int   d_csr[ETOT];
__device__ float d_bsum[F1];
__device__ float d_bsq[F1];
__device__ float d_scale[F1];
__device__ float d_shift[F1];
__device__ int   d_is64;             // edge_index dtype flag (1 = int64, 0 = int32)

// ---------------- dtype detection ------------------------------------------
__global__ void k_detect(const void* ei) {
    if (threadIdx.x == 0) {
        const long long* p = (const long long*)ei;
        int ok64 = 1;
        for (int i = 0; i < 64; i++) {
            long long v = p[i];
            if (v < 0 || v >= NN) { ok64 = 0; break; }
        }
        d_is64 = ok64;
    }
}

__device__ __forceinline__ int load_idx(const void* ei, int i) {
    int v = d_is64 ? (int)((const long long*)ei)[i] : ((const int*)ei)[i];
    v = v < 0 ? 0 : (v >= NN ? NN - 1 : v);
    return v;
}

// ---------------- CSR build ------------------------------------------------
__global__ void k_count(const void* __restrict__ ei) {
    int i = blockIdx.x * blockDim.x + threadIdx.x;
    if (i >= ETOT) return;
    int dst = (i < EE) ? load_idx(ei, EE + i) : (i - EE);
    atomicAdd(&d_deg[dst], 1);
}

__global__ void k_scan() {   // single block, 1024 threads; scan d_deg -> d_off
    __shared__ int s[1024];
    __shared__ int carry;
    int tid = threadIdx.x;
    if (tid == 0) { carry = 0; d_off[0] = 0; }
    __syncthreads();
    for (int base = 0; base < NN; base += 1024) {
        int i = base + tid;
        int v = (i < NN) ? d_deg[i] : 0;
        s[tid] = v;
        __syncthreads();
        #pragma unroll
        for (int ofs = 1; ofs < 1024; ofs <<= 1) {
            int t = (tid >= ofs) ? s[tid - ofs] : 0;
            __syncthreads();
            s[tid] += t;
            __syncthreads();
        }
        if (i < NN) d_off[i + 1] = carry + s[tid];
        __syncthreads();
        if (tid == 0) carry += s[1023];
        __syncthreads();
    }
}

__global__ void k_scatter(const void* __restrict__ ei) {
    int i = blockIdx.x * blockDim.x + threadIdx.x;
    if (i >= ETOT) return;
    int src, dst;
    if (i < EE) { src = load_idx(ei, i); dst = load_idx(ei, EE + i); }
    else        { src = dst = i - EE; }
    int p = d_off[dst] + atomicAdd(&d_cnt[dst], 1);
    d_csr[p] = src;
}

// ---------------- tf32 tensor-core GEMM (3-pass split for fp32 accuracy) ---
// C[M,N] = A[M,K] @ B[K,N], row-major. Block tile 128x128, K-tile 32.
// 8 warps in 2(M)x4(N) layout; each warp owns a 64x32 tile = 4x4 m16n8k8 frags.
// Precision: a = a_hi + a_lo (tf32 truncation); acc += ah*bh + ah*bl + al*bh
// -> ~2^-22 relative error, indistinguishable from fp32 at rel_err 1e-3.
#define A_LD 36    // 128 rows; banks (36*g + c) % 32 = 4g + c -> conflict-free frags
#define B_LD 136   // 32 rows;  banks (136*c + g) % 32 = 8c + g -> conflict-free frags

__device__ __forceinline__ void split_tf32(float v, unsigned& hi, unsigned& lo) {
    unsigned b = __float_as_uint(v);
    hi = b & 0xffffe000u;
    float l = v - __uint_as_float(hi);
    lo = __float_as_uint(l) & 0xffffe000u;
}

__device__ __forceinline__ void mma8(float* d, const unsigned* a, const unsigned* b) {
    asm volatile(
        "mma.sync.aligned.m16n8k8.row.col.f32.tf32.tf32.f32 "
        "{%0,%1,%2,%3}, {%4,%5,%6,%7}, {%8,%9}, {%0,%1,%2,%3};\n"
        : "+f"(d[0]), "+f"(d[1]), "+f"(d[2]), "+f"(d[3])
        : "r"(a[0]), "r"(a[1]), "r"(a[2]), "r"(a[3]), "r"(b[0]), "r"(b[1]));
}

__global__ __launch_bounds__(256)
void gemm_tf32(const float* __restrict__ A, const float* __restrict__ B,
               float* __restrict__ C, int M, int N, int K) {
    __shared__ float sA[128 * A_LD];
    __shared__ float sB[32 * B_LD];
    const int tid  = threadIdx.x;
    const int lane = tid & 31;
    const int warp = tid >> 5;
    const int g = lane >> 2;           // 0..7
    const int c = lane & 3;            // 0..3
    const int warpM = (warp & 1) * 64;
    const int warpN = (warp >> 1) * 32;
    const int blockM = blockIdx.y * 128;
    const int blockN = blockIdx.x * 128;

    float acc[4][4][4];
    #pragma unroll
    for (int mt = 0; mt < 4; mt++)
        #pragma unroll
        for (int nt = 0; nt < 4; nt++)
            #pragma unroll
            for (int i = 0; i < 4; i++) acc[mt][nt][i] = 0.f;

    for (int k0 = 0; k0 < K; k0 += 32) {
        // Load A tile [128 x 32] (row-major, LD=36)
        #pragma unroll
        for (int i = 0; i < 4; i++) {
            int linear = i * 256 + tid;
            int r  = linear >> 3;
            int kq = (linear & 7) << 2;
            int gRow = blockM + r;
            float4 v = make_float4(0.f, 0.f, 0.f, 0.f);
            if (gRow < M) v = *(const float4*)(A + (size_t)gRow * K + k0 + kq);
            *(float4*)&sA[r * A_LD + kq] = v;   // 36*4 and kq*4 both 16B-multiples
        }
        // Load B tile [32 x 128] (row-major, LD=136)
        #pragma unroll
        for (int i = 0; i < 4; i++) {
            int linear = i * 256 + tid;
            int kk = linear >> 5;
            int nq = (linear & 31) << 2;
            float4 v = *(const float4*)(B + (size_t)(k0 + kk) * N + blockN + nq);
            *(float4*)&sB[kk * B_LD + nq] = v;
        }
        __syncthreads();

        #pragma unroll
        for (int ks = 0; ks < 4; ks++) {
            const int kb = ks * 8;
            unsigned ah[4][4], al[4][4], bh[4][2], bl[4][2];
            #pragma unroll
            for (int mt = 0; mt < 4; mt++) {
                int row = warpM + mt * 16;
                float a0 = sA[(row + g)     * A_LD + kb + c];
                float a1 = sA[(row + g + 8) * A_LD + kb + c];
                float a2 = sA[(row + g)     * A_LD + kb + c + 4];
                float a3 = sA[(row + g + 8) * A_LD + kb + c + 4];
                split_tf32(a0, ah[mt][0], al[mt][0]);
                split_tf32(a1, ah[mt][1], al[mt][1]);
                split_tf32(a2, ah[mt][2], al[mt][2]);
                split_tf32(a3, ah[mt][3], al[mt][3]);
            }
            #pragma unroll
            for (int nt = 0; nt < 4; nt++) {
                int col = warpN + nt * 8;
                float b0 = sB[(kb + c)     * B_LD + col + g];
                float b1 = sB[(kb + c + 4) * B_LD + col + g];
                split_tf32(b0, bh[nt][0], bl[nt][0]);
                split_tf32(b1, bh[nt][1], bl[nt][1]);
            }
            #pragma unroll
            for (int mt = 0; mt < 4; mt++)
                #pragma unroll
                for (int nt = 0; nt < 4; nt++) {
                    mma8(acc[mt][nt], ah[mt], bh[nt]);   // hi*hi
                    mma8(acc[mt][nt], ah[mt], bl[nt]);   // hi*lo
                    mma8(acc[mt][nt], al[mt], bh[nt]);   // lo*hi
                }
        }
        __syncthreads();
    }

    // Epilogue: c0,c1 -> (row=g, cols 2c,2c+1); c2,c3 -> row g+8
    #pragma unroll
    for (int mt = 0; mt < 4; mt++)
        #pragma unroll
        for (int nt = 0; nt < 4; nt++) {
            int row0 = blockM + warpM + mt * 16 + g;
            int col  = blockN + warpN + nt * 8 + 2 * c;
            if (row0 < M)
                *(float2*)(C + (size_t)row0 * N + col) =
                    make_float2(acc[mt][nt][0], acc[mt][nt][1]);
            int row1 = row0 + 8;
            if (row1 < M)
                *(float2*)(C + (size_t)row1 * N + col) =
                    make_float2(acc[mt][nt][2], acc[mt][nt][3]);
        }
}

// ---------------- attention coefficients -----------------------------------
__global__ void k_attn1(const float* __restrict__ atts, const float* __restrict__ attd) {
    int n = blockIdx.x;
    int w = threadIdx.x >> 5, l = threadIdx.x & 31;
    const float* hp = d_h1 + (size_t)n * F1 + w * C1C;
    float ss = 0.f, sd = 0.f;
    for (int c = l; c < C1C; c += 32) {
        float v = hp[c];
        ss += v * atts[w * C1C + c];
        sd += v * attd[w * C1C + c];
    }
    #pragma unroll
    for (int o = 16; o; o >>= 1) {
        ss += __shfl_down_sync(0xffffffffu, ss, o);
        sd += __shfl_down_sync(0xffffffffu, sd, o);
    }
    if (!l) { d_as1[n * H1H + w] = ss; d_ad1[n * H1H + w] = sd; }
}

__global__ void k_attn2(const float* __restrict__ atts, const float* __restrict__ attd) {
    int n = blockIdx.x;
    int l = threadIdx.x;
    const float* hp = d_h2 + (size_t)n * F2;
    float ss = 0.f, sd = 0.f;
    for (int c = l; c < F2; c += 32) {
        float v = hp[c];
        ss += v * atts[c];
        sd += v * attd[c];
    }
    #pragma unroll
    for (int o = 16; o; o >>= 1) {
        ss += __shfl_down_sync(0xffffffffu, ss, o);
        sd += __shfl_down_sync(0xffffffffu, sd, o);
    }
    if (!l) { d_as2[n] = ss; d_ad2[n] = sd; }
}

// ---------------- GAT aggregation (CSR per-dst-node, local softmax) --------
__device__ __forceinline__ void sAtomicMaxF(float* a, float v) {
    int* ai = (int*)a;
    int old = *ai;
    while (__int_as_float(old) < v) {
        int assumed = old;
        old = atomicCAS(ai, assumed, __float_as_int(v));
        if (old == assumed) break;
    }
}

__global__ __launch_bounds__(256)
void k_agg1(const float* __restrict__ bias) {
    int n = blockIdx.x;
    int s0 = d_off[n];
    int deg = d_off[n + 1] - s0;
    __shared__ float sm[H1H], sz[H1H], sad[H1H];
    int tid = threadIdx.x;
    if (tid < H1H) { sad[tid] = d_ad1[n * H1H + tid]; sm[tid] = -1e30f; sz[tid] = 0.f; }
    __syncthreads();
    for (int idx = tid; idx < deg * H1H; idx += 256) {
        int e = idx >> 3, hh = idx & 7;
        int src = d_csr[s0 + e];
        float v = d_as1[src * H1H + hh] + sad[hh];
        v = v > 0.f ? v : NEG * v;
        sAtomicMaxF(&sm[hh], v);
    }
    __syncthreads();
    for (int idx = tid; idx < deg * H1H; idx += 256) {
        int e = idx >> 3, hh = idx & 7;
        int src = d_csr[s0 + e];
        float v = d_as1[src * H1H + hh] + sad[hh];
        v = v > 0.f ? v : NEG * v;
        atomicAdd(&sz[hh], __expf(v - sm[hh]));
    }
    __syncthreads();
    int c0 = tid * 4;
    int hh = c0 >> 7;
    float m = sm[hh], invz = 1.f / sz[hh], ad = sad[hh];
    float4 acc = make_float4(0.f, 0.f, 0.f, 0.f);
    for (int e = 0; e < deg; e++) {
        int src = d_csr[s0 + e];
        float v = d_as1[src * H1H + hh] + ad;
        v = v > 0.f ? v : NEG * v;
        float al = __expf(v - m) * invz;
        float4 hv = *(const float4*)(d_h1 + (size_t)src * F1 + c0);
        acc.x += al * hv.x; acc.y += al * hv.y;
        acc.z += al * hv.z; acc.w += al * hv.w;
    }
    float4 bb = *(const float4*)(bias + c0);
    acc.x += bb.x; acc.y += bb.y; acc.z += bb.z; acc.w += bb.w;
    *(float4*)(d_g1 + (size_t)n * F1 + c0) = acc;
}

__global__ __launch_bounds__(128)
void k_agg2(const float* __restrict__ bias) {
    int n = blockIdx.x;
    int s0 = d_off[n];
    int deg = d_off[n + 1] - s0;
    __shared__ float sm, sz, sad;
    int tid = threadIdx.x;
    if (tid == 0) { sad = d_ad2[n]; sm = -1e30f; sz = 0.f; }
    __syncthreads();
    for (int e = tid; e < deg; e += 128) {
        float v = d_as2[d_csr[s0 + e]] + sad;
        v = v > 0.f ? v : NEG * v;
        sAtomicMaxF(&sm, v);
    }
    __syncthreads();
    for (int e = tid; e < deg; e += 128) {
        float v = d_as2[d_csr[s0 + e]] + sad;
        v = v > 0.f ? v : NEG * v;
        atomicAdd(&sz, __expf(v - sm));
    }
    __syncthreads();
    float m = sm, invz = 1.f / sz, ad = sad;
    float acc = 0.f;
    for (int e = 0; e < deg; e++) {
        int src = d_csr[s0 + e];
        float v = d_as2[src] + ad;
        v = v > 0.f ? v : NEG * v;
        acc += __expf(v - m) * invz * d_h2[(size_t)src * F2 + tid];
    }
    d_g2[(size_t)n * F2 + tid] = acc + bias[tid];
}

// ---------------- BatchNorm + ELU ------------------------------------------
__global__ void bn_stats(const float* __restrict__ x, float* __restrict__ sum,
                         float* __restrict__ sq, int F) {
    int col = blockIdx.x * 128 + threadIdx.x;
    float s = 0.f, q = 0.f;
    for (int r = blockIdx.y; r < NN; r += gridDim.y) {
        float v = x[(size_t)r * F + col];
        s += v; q += v * v;
    }
    atomicAdd(&sum[col], s);
    atomicAdd(&sq[col], q);
}

__global__ void bn_final(const float* __restrict__ sum, const float* __restrict__ sq,
                         const float* __restrict__ gamma, const float* __restrict__ beta,
                         float* __restrict__ scale, float* __restrict__ shift, int F) {
    int c = blockIdx.x * blockDim.x + threadIdx.x;
    if (c < F) {
        float mu  = sum[c] * (1.f / NN);
        float var = sq[c] * (1.f / NN) - mu * mu;
        float sc  = gamma[c] * rsqrtf(var + BNEPS);
        scale[c] = sc;
        shift[c] = beta[c] - mu * sc;
    }
}

__global__ void bn_apply_elu(float* __restrict__ x, const float* __restrict__ scale,
                             const float* __restrict__ shift, int mask, int total) {
    int i = blockIdx.x * blockDim.x + threadIdx.x;
    if (i < total) {
        int c = i & mask;
        float v = x[i] * scale[c] + shift[c];
        x[i] = v > 0.f ? v : (__expf(v) - 1.f);
    }
}

// ---------------- classifier head ------------------------------------------
__global__ __launch_bounds__(64)
void k_classifier(const float* __restrict__ g2, const float* __restrict__ Wc1,
                  const float* __restrict__ bc1, const float* __restrict__ Wc2,
                  const float* __restrict__ bc2, float* __restrict__ out) {
    int n = blockIdx.x;
    int tid = threadIdx.x;
    __shared__ float sx[128], sh[64];
    sx[tid]      = g2[(size_t)n * F2 + tid];
    sx[tid + 64] = g2[(size_t)n * F2 + 64 + tid];
    __syncthreads();
    float s = bc1[tid];
    #pragma unroll 8
    for (int k = 0; k < 128; k++) s += sx[k] * Wc1[k * 64 + tid];
    sh[tid] = fmaxf(s, 0.f);
    __syncthreads();
    if (tid < 2) {
        float o = bc2[tid];
        #pragma unroll 8
        for (int k = 0; k < 64; k++) o += sh[k] * Wc2[k * 2 + tid];
        out[n * 2 + tid] = o;
    }
}

// ---------------- launch ----------------------------------------------------
extern "C" void kernel_launch(void* const* d_in, const int* in_sizes, int n_in,
                              void* d_out, int out_size) {
    const float* x     = (const float*)d_in[0];
    const void*  ei    = d_in[1];                 // int32 or int64 — detected on device
    const float* W1    = (const float*)d_in[2];
    const float* atts1 = (const float*)d_in[3];
    const float* attd1 = (const float*)d_in[4];
    const float* b1    = (const float*)d_in[5];
    const float* W2    = (const float*)d_in[6];
    const float* atts2 = (const float*)d_in[7];
    const float* attd2 = (const float*)d_in[8];
    const float* b2    = (const float*)d_in[9];
    const float* g1    = (const float*)d_in[10];
    const float* be1   = (const float*)d_in[11];
    const float* g2w   = (const float*)d_in[12];
    const float* be2   = (const float*)d_in[13];
    const float* Wc1   = (const float*)d_in[14];
    const float* bc1   = (const float*)d_in[15];
    const float* Wc2   = (const float*)d_in[16];
    const float* bc2   = (const float*)d_in[17];
    float*       out   = (float*)d_out;

    void *p_deg, *p_cnt, *p_h1, *p_g1, *p_h2, *p_g2, *p_bsum, *p_bsq, *p_scale, *p_shift;
    cudaGetSymbolAddress(&p_deg,   d_deg);
    cudaGetSymbolAddress(&p_cnt,   d_cnt);
    cudaGetSymbolAddress(&p_h1,    d_h1);
    cudaGetSymbolAddress(&p_g1,    d_g1);
    cudaGetSymbolAddress(&p_h2,    d_h2);
    cudaGetSymbolAddress(&p_g2,    d_g2);
    cudaGetSymbolAddress(&p_bsum,  d_bsum);
    cudaGetSymbolAddress(&p_bsq,   d_bsq);
    cudaGetSymbolAddress(&p_scale, d_scale);
    cudaGetSymbolAddress(&p_shift, d_shift);

    // CSR build
    cudaMemsetAsync(p_deg, 0, NN * sizeof(int));
    cudaMemsetAsync(p_cnt, 0, NN * sizeof(int));
    k_detect<<<1, 32>>>(ei);
    k_count<<<(ETOT + 255) / 256, 256>>>(ei);
    k_scan<<<1, 1024>>>();
    k_scatter<<<(ETOT + 255) / 256, 256>>>(ei);

    // ---- GAT layer 1 ----
    {
        dim3 grid(F1 / 128, (NN + 127) / 128);
        gemm_tf32<<<grid, 256>>>(x, W1, (float*)p_h1, NN, F1, DIN);
    }
    k_attn1<<<NN, 256>>>(atts1, attd1);
    k_agg1<<<NN, 256>>>(b1);

    // BN1 + ELU (in place on d_g1)
    cudaMemsetAsync(p_bsum, 0, F1 * sizeof(float));
    cudaMemsetAsync(p_bsq,  0, F1 * sizeof(float));
    {
        dim3 grid(F1 / 128, 128);
        bn_stats<<<grid, 128>>>((const float*)p_g1, (float*)p_bsum, (float*)p_bsq, F1);
    }
    bn_final<<<F1 / 128, 128>>>((const float*)p_bsum, (const float*)p_bsq, g1, be1,
                                (float*)p_scale, (float*)p_shift, F1);
    bn_apply_elu<<<(NN * F1 + 255) / 256, 256>>>((float*)p_g1, (const float*)p_scale,
                                                 (const float*)p_shift, F1 - 1, NN * F1);

    // ---- GAT layer 2 ----
    {
        dim3 grid(F2 / 128, (NN + 127) / 128);
        gemm_tf32<<<grid, 256>>>((const float*)p_g1, W2, (float*)p_h2, NN, F2, F1);
    }
    k_attn2<<<NN, 32>>>(atts2, attd2);
    k_agg2<<<NN, 128>>>(b2);

    // BN2 + ELU (in place on d_g2)
    cudaMemsetAsync(p_bsum, 0, F2 * sizeof(float));
    cudaMemsetAsync(p_bsq,  0, F2 * sizeof(float));
    {
        dim3 grid(F2 / 128, 128);
        bn_stats<<<grid, 128>>>((const float*)p_g2, (float*)p_bsum, (float*)p_bsq, F2);
    }
    bn_final<<<1, 128>>>((const float*)p_bsum, (const float*)p_bsq, g2w, be2,
                         (float*)p_scale, (float*)p_shift, F2);
    bn_apply_elu<<<(NN * F2 + 255) / 256, 256>>>((float*)p_g2, (const float*)p_scale,
                                                 (const float*)p_shift, F2 - 1, NN * F2);

    // ---- classifier head ----
    k_classifier<<<NN, 64>>>((const float*)p_g2, Wc1, bc1, Wc2, bc2, out);
}

// round 5
// speedup vs baseline: 1.3581x; 1.1903x over previous
#include <cuda_runtime.h>

// Problem constants (fixed shapes)
#define NN   20000
#define EE   320000
#define ETOT 340000      // EE + NN self-loops
#define DIN  768
#define F1   1024        // H1*C1
#define H1H  8
#define C1C  128
#define F2   128
#define NEG  0.2f
#define BNEPS 1e-5f

// ---------------- scratch (device globals; no allocation allowed) ----------
__device__ float d_h1[NN * F1];      // x @ W1            (81.9 MB)
__device__ float d_g1[NN * F1];      // GAT1 out -> BN/ELU in place
__device__ float d_h2[NN * F2];      // g1 @ W2
__device__ float d_g2[NN * F2];      // GAT2 out -> BN/ELU in place
__device__ float d_as1[NN * H1H];
__device__ float d_ad1[NN * H1H];
__device__ float d_as2[NN];
__device__ float d_ad2[NN];
__device__ int   d_deg[NN];
__device__ int   d_off[NN + 1];
__device__ int   d_cnt[NN];
__device__ int   d_csr[ETOT];
__device__ float d_bsum[F1];
__device__ float d_bsq[F1];
__device__ float d_scale[F1];
__device__ float d_shift[F1];
__device__ int   d_is64;             // edge_index dtype flag (1 = int64, 0 = int32)

// ---------------- dtype detection ------------------------------------------
__global__ void k_detect(const void* ei) {
    if (threadIdx.x == 0) {
        const long long* p = (const long long*)ei;
        int ok64 = 1;
        for (int i = 0; i < 64; i++) {
            long long v = p[i];
            if (v < 0 || v >= NN) { ok64 = 0; break; }
        }
        d_is64 = ok64;
    }
}

__device__ __forceinline__ int load_idx(const void* ei, int i) {
    int v = d_is64 ? (int)((const long long*)ei)[i] : ((const int*)ei)[i];
    v = v < 0 ? 0 : (v >= NN ? NN - 1 : v);
    return v;
}

// ---------------- CSR build ------------------------------------------------
__global__ void k_count(const void* __restrict__ ei) {
    int i = blockIdx.x * blockDim.x + threadIdx.x;
    if (i >= ETOT) return;
    int dst = (i < EE) ? load_idx(ei, EE + i) : (i - EE);
    atomicAdd(&d_deg[dst], 1);
}

__global__ void k_scan() {   // single block, 1024 threads; scan d_deg -> d_off
    __shared__ int s[1024];
    __shared__ int carry;
    int tid = threadIdx.x;
    if (tid == 0) { carry = 0; d_off[0] = 0; }
    __syncthreads();
    for (int base = 0; base < NN; base += 1024) {
        int i = base + tid;
        int v = (i < NN) ? d_deg[i] : 0;
        s[tid] = v;
        __syncthreads();
        #pragma unroll
        for (int ofs = 1; ofs < 1024; ofs <<= 1) {
            int t = (tid >= ofs) ? s[tid - ofs] : 0;
            __syncthreads();
            s[tid] += t;
            __syncthreads();
        }
        if (i < NN) d_off[i + 1] = carry + s[tid];
        __syncthreads();
        if (tid == 0) carry += s[1023];
        __syncthreads();
    }
    // zero d_cnt here (scatter runs in a later kernel) -> saves one memset launch
    for (int i = tid; i < NN; i += 1024) d_cnt[i] = 0;
}

__global__ void k_scatter(const void* __restrict__ ei) {
    int i = blockIdx.x * blockDim.x + threadIdx.x;
    if (i >= ETOT) return;
    int src, dst;
    if (i < EE) { src = load_idx(ei, i); dst = load_idx(ei, EE + i); }
    else        { src = dst = i - EE; }
    int p = d_off[dst] + atomicAdd(&d_cnt[dst], 1);
    d_csr[p] = src;
}

// ---------------- tf32 tensor-core GEMM, cp.async double-buffered ----------
// C[M,N] = A[M,K] @ B[K,N], row-major. Block tile 128x128, K-tile 32, 2 stages.
// 8 warps in 2(M)x4(N) layout; each warp owns a 64x32 tile = 4x4 m16n8k8 frags.
// Precision: a = a_hi + a_lo (tf32 truncation); acc += ah*bh + ah*bl + al*bh.
#define A_LD 36    // banks (36*g + c) % 32 = 4g + c -> conflict-free frags
#define B_LD 136   // banks (136*c + g) % 32 = 8c + g -> conflict-free frags
#define STG_FLOATS (128 * A_LD + 32 * B_LD)          // 8960 floats per stage
#define GEMM_SMEM  (2 * STG_FLOATS * (int)sizeof(float))  // 71680 bytes

__device__ __forceinline__ void split_tf32(float v, unsigned& hi, unsigned& lo) {
    unsigned b = __float_as_uint(v);
    hi = b & 0xffffe000u;
    float l = v - __uint_as_float(hi);
    lo = __float_as_uint(l) & 0xffffe000u;
}

__device__ __forceinline__ void mma8(float* d, const unsigned* a, const unsigned* b) {
    asm volatile(
        "mma.sync.aligned.m16n8k8.row.col.f32.tf32.tf32.f32 "
        "{%0,%1,%2,%3}, {%4,%5,%6,%7}, {%8,%9}, {%0,%1,%2,%3};\n"
        : "+f"(d[0]), "+f"(d[1]), "+f"(d[2]), "+f"(d[3])
        : "r"(a[0]), "r"(a[1]), "r"(a[2]), "r"(a[3]), "r"(b[0]), "r"(b[1]));
}

__device__ __forceinline__ void cpasync16(void* smem_dst, const void* gsrc, int srcsize) {
    unsigned dst = (unsigned)__cvta_generic_to_shared(smem_dst);
    asm volatile("cp.async.cg.shared.global [%0], [%1], 16, %2;\n"
                 :: "r"(dst), "l"(gsrc), "r"(srcsize));
}

__global__ __launch_bounds__(256)
void gemm_tf32(const float* __restrict__ A, const float* __restrict__ B,
               float* __restrict__ C, int M, int N, int K) {
    extern __shared__ float smem[];
    const int tid  = threadIdx.x;
    const int lane = tid & 31;
    const int warp = tid >> 5;
    const int g = lane >> 2;           // 0..7
    const int c = lane & 3;            // 0..3
    const int warpM = (warp & 1) * 64;
    const int warpN = (warp >> 1) * 32;
    const int blockM = blockIdx.y * 128;
    const int blockN = blockIdx.x * 128;

    // per-thread load coordinates (fixed across tiles)
    const int aR  = tid >> 1;               // 0..127
    const int aKq = (tid & 1) * 16;         // two float4 slots per row half? (see below)
    // A tile: 128 rows x 32 cols = 1024 float4; 256 threads x 4 each
    // mapping i in 0..3: linear = i*256+tid; r=linear>>3; kq=(linear&7)*4
    // B tile: 32 rows x 128 cols = 1024 float4; kk=linear>>5; nq=(linear&31)*4

    float acc[4][4][4];
    #pragma unroll
    for (int mt = 0; mt < 4; mt++)
        #pragma unroll
        for (int nt = 0; nt < 4; nt++)
            #pragma unroll
            for (int i = 0; i < 4; i++) acc[mt][nt][i] = 0.f;

    const int T = K >> 5;   // K/32 tiles

    // ---- stage loader ----
    auto load_stage = [&](int t, int stg) {
        float* sA = smem + stg * STG_FLOATS;
        float* sB = sA + 128 * A_LD;
        const int k0 = t << 5;
        #pragma unroll
        for (int i = 0; i < 4; i++) {
            int linear = i * 256 + tid;
            int r  = linear >> 3;
            int kq = (linear & 7) << 2;
            int gRow = blockM + r;
            cpasync16(&sA[r * A_LD + kq],
                      A + (size_t)gRow * K + k0 + kq,
                      (gRow < M) ? 16 : 0);
        }
        #pragma unroll
        for (int i = 0; i < 4; i++) {
            int linear = i * 256 + tid;
            int kk = linear >> 5;
            int nq = (linear & 31) << 2;
            cpasync16(&sB[kk * B_LD + nq],
                      B + (size_t)(k0 + kk) * N + blockN + nq, 16);
        }
    };

    load_stage(0, 0);
    asm volatile("cp.async.commit_group;\n" ::);

    for (int t = 0; t < T; t++) {
        const int cur = t & 1;
        if (t + 1 < T) {
            load_stage(t + 1, (t + 1) & 1);
            asm volatile("cp.async.commit_group;\n" ::);
            asm volatile("cp.async.wait_group 1;\n" ::);
        } else {
            asm volatile("cp.async.wait_group 0;\n" ::);
        }
        __syncthreads();

        const float* sA = smem + cur * STG_FLOATS;
        const float* sB = sA + 128 * A_LD;

        #pragma unroll
        for (int ks = 0; ks < 4; ks++) {
            const int kb = ks * 8;
            unsigned ah[4][4], al[4][4], bh[4][2], bl[4][2];
            #pragma unroll
            for (int mt = 0; mt < 4; mt++) {
                int row = warpM + mt * 16;
                float a0 = sA[(row + g)     * A_LD + kb + c];
                float a1 = sA[(row + g + 8) * A_LD + kb + c];
                float a2 = sA[(row + g)     * A_LD + kb + c + 4];
                float a3 = sA[(row + g + 8) * A_LD + kb + c + 4];
                split_tf32(a0, ah[mt][0], al[mt][0]);
                split_tf32(a1, ah[mt][1], al[mt][1]);
                split_tf32(a2, ah[mt][2], al[mt][2]);
                split_tf32(a3, ah[mt][3], al[mt][3]);
            }
            #pragma unroll
            for (int nt = 0; nt < 4; nt++) {
                int col = warpN + nt * 8;
                float b0 = sB[(kb + c)     * B_LD + col + g];
                float b1 = sB[(kb + c + 4) * B_LD + col + g];
                split_tf32(b0, bh[nt][0], bl[nt][0]);
                split_tf32(b1, bh[nt][1], bl[nt][1]);
            }
            #pragma unroll
            for (int mt = 0; mt < 4; mt++)
                #pragma unroll
                for (int nt = 0; nt < 4; nt++) {
                    mma8(acc[mt][nt], ah[mt], bh[nt]);   // hi*hi
                    mma8(acc[mt][nt], ah[mt], bl[nt]);   // hi*lo
                    mma8(acc[mt][nt], al[mt], bh[nt]);   // lo*hi
                }
        }
        __syncthreads();   // protect cur buffer before it is reloaded at t+2
    }

    // Epilogue: c0,c1 -> (row=g, cols 2c,2c+1); c2,c3 -> row g+8
    #pragma unroll
    for (int mt = 0; mt < 4; mt++)
        #pragma unroll
        for (int nt = 0; nt < 4; nt++) {
            int row0 = blockM + warpM + mt * 16 + g;
            int col  = blockN + warpN + nt * 8 + 2 * c;
            if (row0 < M)
                *(float2*)(C + (size_t)row0 * N + col) =
                    make_float2(acc[mt][nt][0], acc[mt][nt][1]);
            int row1 = row0 + 8;
            if (row1 < M)
                *(float2*)(C + (size_t)row1 * N + col) =
                    make_float2(acc[mt][nt][2], acc[mt][nt][3]);
        }
}

// ---------------- attention coefficients -----------------------------------
__global__ void k_attn1(const float* __restrict__ atts, const float* __restrict__ attd) {
    int n = blockIdx.x;
    int w = threadIdx.x >> 5, l = threadIdx.x & 31;
    const float* hp = d_h1 + (size_t)n * F1 + w * C1C;
    float ss = 0.f, sd = 0.f;
    for (int c = l; c < C1C; c += 32) {
        float v = hp[c];
        ss += v * atts[w * C1C + c];
        sd += v * attd[w * C1C + c];
    }
    #pragma unroll
    for (int o = 16; o; o >>= 1) {
        ss += __shfl_down_sync(0xffffffffu, ss, o);
        sd += __shfl_down_sync(0xffffffffu, sd, o);
    }
    if (!l) { d_as1[n * H1H + w] = ss; d_ad1[n * H1H + w] = sd; }
}

__global__ void k_attn2(const float* __restrict__ atts, const float* __restrict__ attd) {
    int n = blockIdx.x;
    int l = threadIdx.x;
    const float* hp = d_h2 + (size_t)n * F2;
    float ss = 0.f, sd = 0.f;
    for (int c = l; c < F2; c += 32) {
        float v = hp[c];
        ss += v * atts[c];
        sd += v * attd[c];
    }
    #pragma unroll
    for (int o = 16; o; o >>= 1) {
        ss += __shfl_down_sync(0xffffffffu, ss, o);
        sd += __shfl_down_sync(0xffffffffu, sd, o);
    }
    if (!l) { d_as2[n] = ss; d_ad2[n] = sd; }
}

// ---------------- GAT aggregation (CSR per-dst-node, local softmax) --------
__device__ __forceinline__ void sAtomicMaxF(float* a, float v) {
    int* ai = (int*)a;
    int old = *ai;
    while (__int_as_float(old) < v) {
        int assumed = old;
        old = atomicCAS(ai, assumed, __float_as_int(v));
        if (old == assumed) break;
    }
}

__global__ __launch_bounds__(256)
void k_agg1(const float* __restrict__ bias) {
    int n = blockIdx.x;
    int s0 = d_off[n];
    int deg = d_off[n + 1] - s0;
    __shared__ float sm[H1H], sz[H1H], sad[H1H];
    int tid = threadIdx.x;
    if (tid < H1H) { sad[tid] = d_ad1[n * H1H + tid]; sm[tid] = -1e30f; sz[tid] = 0.f; }
    __syncthreads();
    for (int idx = tid; idx < deg * H1H; idx += 256) {
        int e = idx >> 3, hh = idx & 7;
        int src = d_csr[s0 + e];
        float v = d_as1[src * H1H + hh] + sad[hh];
        v = v > 0.f ? v : NEG * v;
        sAtomicMaxF(&sm[hh], v);
    }
    __syncthreads();
    for (int idx = tid; idx < deg * H1H; idx += 256) {
        int e = idx >> 3, hh = idx & 7;
        int src = d_csr[s0 + e];
        float v = d_as1[src * H1H + hh] + sad[hh];
        v = v > 0.f ? v : NEG * v;
        atomicAdd(&sz[hh], __expf(v - sm[hh]));
    }
    __syncthreads();
    int c0 = tid * 4;
    int hh = c0 >> 7;
    float m = sm[hh], invz = 1.f / sz[hh], ad = sad[hh];
    float4 acc = make_float4(0.f, 0.f, 0.f, 0.f);
    for (int e = 0; e < deg; e++) {
        int src = d_csr[s0 + e];
        float v = d_as1[src * H1H + hh] + ad;
        v = v > 0.f ? v : NEG * v;
        float al = __expf(v - m) * invz;
        float4 hv = *(const float4*)(d_h1 + (size_t)src * F1 + c0);
        acc.x += al * hv.x; acc.y += al * hv.y;
        acc.z += al * hv.z; acc.w += al * hv.w;
    }
    float4 bb = *(const float4*)(bias + c0);
    acc.x += bb.x; acc.y += bb.y; acc.z += bb.z; acc.w += bb.w;
    *(float4*)(d_g1 + (size_t)n * F1 + c0) = acc;
}

__global__ __launch_bounds__(128)
void k_agg2(const float* __restrict__ bias) {
    int n = blockIdx.x;
    int s0 = d_off[n];
    int deg = d_off[n + 1] - s0;
    __shared__ float sm, sz, sad;
    int tid = threadIdx.x;
    if (tid == 0) { sad = d_ad2[n]; sm = -1e30f; sz = 0.f; }
    __syncthreads();
    for (int e = tid; e < deg; e += 128) {
        float v = d_as2[d_csr[s0 + e]] + sad;
        v = v > 0.f ? v : NEG * v;
        sAtomicMaxF(&sm, v);
    }
    __syncthreads();
    for (int e = tid; e < deg; e += 128) {
        float v = d_as2[d_csr[s0 + e]] + sad;
        v = v > 0.f ? v : NEG * v;
        atomicAdd(&sz, __expf(v - sm));
    }
    __syncthreads();
    float m = sm, invz = 1.f / sz, ad = sad;
    float acc = 0.f;
    for (int e = 0; e < deg; e++) {
        int src = d_csr[s0 + e];
        float v = d_as2[src] + ad;
        v = v > 0.f ? v : NEG * v;
        acc += __expf(v - m) * invz * d_h2[(size_t)src * F2 + tid];
    }
    d_g2[(size_t)n * F2 + tid] = acc + bias[tid];
}

// ---------------- BatchNorm + ELU ------------------------------------------
__global__ void bn_stats(const float* __restrict__ x, float* __restrict__ sum,
                         float* __restrict__ sq, int F) {
    int col = blockIdx.x * 128 + threadIdx.x;
    float s = 0.f, q = 0.f;
    for (int r = blockIdx.y; r < NN; r += gridDim.y) {
        float v = x[(size_t)r * F + col];
        s += v; q += v * v;
    }
    atomicAdd(&sum[col], s);
    atomicAdd(&sq[col], q);
}

__global__ void bn_final(const float* __restrict__ sum, const float* __restrict__ sq,
                         const float* __restrict__ gamma, const float* __restrict__ beta,
                         float* __restrict__ scale, float* __restrict__ shift, int F) {
    int c = blockIdx.x * blockDim.x + threadIdx.x;
    if (c < F) {
        float mu  = sum[c] * (1.f / NN);
        float var = sq[c] * (1.f / NN) - mu * mu;
        float sc  = gamma[c] * rsqrtf(var + BNEPS);
        scale[c] = sc;
        shift[c] = beta[c] - mu * sc;
    }
}

__global__ void bn_apply_elu(float* __restrict__ x, const float* __restrict__ scale,
                             const float* __restrict__ shift, int mask, int total) {
    int i = blockIdx.x * blockDim.x + threadIdx.x;
    if (i < total) {
        int c = i & mask;
        float v = x[i] * scale[c] + shift[c];
        x[i] = v > 0.f ? v : (__expf(v) - 1.f);
    }
}

// ---------------- classifier head ------------------------------------------
__global__ __launch_bounds__(64)
void k_classifier(const float* __restrict__ g2, const float* __restrict__ Wc1,
                  const float* __restrict__ bc1, const float* __restrict__ Wc2,
                  const float* __restrict__ bc2, float* __restrict__ out) {
    int n = blockIdx.x;
    int tid = threadIdx.x;
    __shared__ float sx[128], sh[64];
    sx[tid]      = g2[(size_t)n * F2 + tid];
    sx[tid + 64] = g2[(size_t)n * F2 + 64 + tid];
    __syncthreads();
    float s = bc1[tid];
    #pragma unroll 8
    for (int k = 0; k < 128; k++) s += sx[k] * Wc1[k * 64 + tid];
    sh[tid] = fmaxf(s, 0.f);
    __syncthreads();
    if (tid < 2) {
        float o = bc2[tid];
        #pragma unroll 8
        for (int k = 0; k < 64; k++) o += sh[k] * Wc2[k * 2 + tid];
        out[n * 2 + tid] = o;
    }
}

// ---------------- launch ----------------------------------------------------
extern "C" void kernel_launch(void* const* d_in, const int* in_sizes, int n_in,
                              void* d_out, int out_size) {
    const float* x     = (const float*)d_in[0];
    const void*  ei    = d_in[1];                 // int32 or int64 — detected on device
    const float* W1    = (const float*)d_in[2];
    const float* atts1 = (const float*)d_in[3];
    const float* attd1 = (const float*)d_in[4];
    const float* b1    = (const float*)d_in[5];
    const float* W2    = (const float*)d_in[6];
    const float* atts2 = (const float*)d_in[7];
    const float* attd2 = (const float*)d_in[8];
    const float* b2    = (const float*)d_in[9];
    const float* g1    = (const float*)d_in[10];
    const float* be1   = (const float*)d_in[11];
    const float* g2w   = (const float*)d_in[12];
    const float* be2   = (const float*)d_in[13];
    const float* Wc1   = (const float*)d_in[14];
    const float* bc1   = (const float*)d_in[15];
    const float* Wc2   = (const float*)d_in[16];
    const float* bc2   = (const float*)d_in[17];
    float*       out   = (float*)d_out;

    void *p_deg, *p_h1, *p_g1, *p_h2, *p_g2, *p_bsum, *p_bsq, *p_scale, *p_shift;
    cudaGetSymbolAddress(&p_deg,   d_deg);
    cudaGetSymbolAddress(&p_h1,    d_h1);
    cudaGetSymbolAddress(&p_g1,    d_g1);
    cudaGetSymbolAddress(&p_h2,    d_h2);
    cudaGetSymbolAddress(&p_g2,    d_g2);
    cudaGetSymbolAddress(&p_bsum,  d_bsum);
    cudaGetSymbolAddress(&p_bsq,   d_bsq);
    cudaGetSymbolAddress(&p_scale, d_scale);
    cudaGetSymbolAddress(&p_shift, d_shift);

    cudaFuncSetAttribute(gemm_tf32, cudaFuncAttributeMaxDynamicSharedMemorySize,
                         GEMM_SMEM);

    // CSR build (launch order arranged so gemm_tf32 is the 6th launch -> ncu -s 5)
    cudaMemsetAsync(p_deg, 0, NN * sizeof(int));            // 1
    k_detect<<<1, 32>>>(ei);                                 // 2
    k_count<<<(ETOT + 255) / 256, 256>>>(ei);                // 3
    k_scan<<<1, 1024>>>();                                   // 4 (also zeros d_cnt)
    k_scatter<<<(ETOT + 255) / 256, 256>>>(ei);              // 5

    // ---- GAT layer 1 ----
    {
        dim3 grid(F1 / 128, (NN + 127) / 128);
        gemm_tf32<<<grid, 256, GEMM_SMEM>>>(x, W1, (float*)p_h1, NN, F1, DIN);  // 6
    }
    k_attn1<<<NN, 256>>>(atts1, attd1);
    k_agg1<<<NN, 256>>>(b1);

    // BN1 + ELU (in place on d_g1)
    cudaMemsetAsync(p_bsum, 0, F1 * sizeof(float));
    cudaMemsetAsync(p_bsq,  0, F1 * sizeof(float));
    {
        dim3 grid(F1 / 128, 128);
        bn_stats<<<grid, 128>>>((const float*)p_g1, (float*)p_bsum, (float*)p_bsq, F1);
    }
    bn_final<<<F1 / 128, 128>>>((const float*)p_bsum, (const float*)p_bsq, g1, be1,
                                (float*)p_scale, (float*)p_shift, F1);
    bn_apply_elu<<<(NN * F1 + 255) / 256, 256>>>((float*)p_g1, (const float*)p_scale,
                                                 (const float*)p_shift, F1 - 1, NN * F1);

    // ---- GAT layer 2 ----
    {
        dim3 grid(F2 / 128, (NN + 127) / 128);
        gemm_tf32<<<grid, 256, GEMM_SMEM>>>((const float*)p_g1, W2, (float*)p_h2,
                                            NN, F2, F1);
    }
    k_attn2<<<NN, 32>>>(atts2, attd2);
    k_agg2<<<NN, 128>>>(b2);

    // BN2 + ELU (in place on d_g2)
    cudaMemsetAsync(p_bsum, 0, F2 * sizeof(float));
    cudaMemsetAsync(p_bsq,  0, F2 * sizeof(float));
    {
        dim3 grid(F2 / 128, 128);
        bn_stats<<<grid, 128>>>((const float*)p_g2, (float*)p_bsum, (float*)p_bsq, F2);
    }
    bn_final<<<1, 128>>>((const float*)p_bsum, (const float*)p_bsq, g2w, be2,
                         (float*)p_scale, (float*)p_shift, F2);
    bn_apply_elu<<<(NN * F2 + 255) / 256, 256>>>((float*)p_g2, (const float*)p_scale,
                                                 (const float*)p_shift, F2 - 1, NN * F2);

    // ---- classifier head ----
    k_classifier<<<NN, 64>>>((const float*)p_g2, Wc1, bc1, Wc2, bc2, out);
}

// round 7
// speedup vs baseline: 1.5932x; 1.1732x over previous
#include <cuda_runtime.h>

// Problem constants (fixed shapes)
#define NN   20000
#define EE   320000
#define ETOT 340000      // EE + NN self-loops
#define DIN  768
#define F1   1024        // H1*C1
#define H1H  8
#define C1C  128
#define F2   128
#define NEG  0.2f
#define BNEPS 1e-5f

// ---------------- scratch (device globals; no allocation allowed) ----------
__device__ float d_h1[NN * F1];      // x @ W1            (81.9 MB)
__device__ float d_g1[NN * F1];      // GAT1 out -> BN/ELU in place
__device__ float d_h2[NN * F2];      // g1 @ W2
__device__ float d_g2[NN * F2];      // GAT2 out -> BN/ELU in place
__device__ float d_as1[NN * H1H];
__device__ float d_ad1[NN * H1H];
__device__ float d_as2[NN];
__device__ float d_ad2[NN];
__device__ int   d_deg[NN];
__device__ int   d_off[NN + 1];
__device__ int   d_cnt[NN];
__device__ int   d_csr[ETOT];
__device__ float d_bsum[F1];
__device__ float d_bsq[F1];
__device__ float d_scale[F1];
__device__ float d_shift[F1];
__device__ int   d_is64;             // edge_index dtype flag (1 = int64, 0 = int32)

// ---------------- dtype detection ------------------------------------------
__global__ void k_detect(const void* ei) {
    if (threadIdx.x == 0) {
        const long long* p = (const long long*)ei;
        int ok64 = 1;
        for (int i = 0; i < 64; i++) {
            long long v = p[i];
            if (v < 0 || v >= NN) { ok64 = 0; break; }
        }
        d_is64 = ok64;
    }
}

__device__ __forceinline__ int load_idx(const void* ei, int i) {
    int v = d_is64 ? (int)((const long long*)ei)[i] : ((const int*)ei)[i];
    v = v < 0 ? 0 : (v >= NN ? NN - 1 : v);
    return v;
}

// ---------------- CSR build ------------------------------------------------
__global__ void k_count(const void* __restrict__ ei) {
    int i = blockIdx.x * blockDim.x + threadIdx.x;
    if (i >= ETOT) return;
    int dst = (i < EE) ? load_idx(ei, EE + i) : (i - EE);
    atomicAdd(&d_deg[dst], 1);
}

__global__ void k_scan() {   // single block, 1024 threads; scan d_deg -> d_off
    __shared__ int s[1024];
    __shared__ int carry;
    int tid = threadIdx.x;
    if (tid == 0) { carry = 0; d_off[0] = 0; }
    __syncthreads();
    for (int base = 0; base < NN; base += 1024) {
        int i = base + tid;
        int v = (i < NN) ? d_deg[i] : 0;
        s[tid] = v;
        __syncthreads();
        #pragma unroll
        for (int ofs = 1; ofs < 1024; ofs <<= 1) {
            int t = (tid >= ofs) ? s[tid - ofs] : 0;
            __syncthreads();
            s[tid] += t;
            __syncthreads();
        }
        if (i < NN) d_off[i + 1] = carry + s[tid];
        __syncthreads();
        if (tid == 0) carry += s[1023];
        __syncthreads();
    }
    for (int i = tid; i < NN; i += 1024) d_cnt[i] = 0;
}

__global__ void k_scatter(const void* __restrict__ ei) {
    int i = blockIdx.x * blockDim.x + threadIdx.x;
    if (i >= ETOT) return;
    int src, dst;
    if (i < EE) { src = load_idx(ei, i); dst = load_idx(ei, EE + i); }
    else        { src = dst = i - EE; }
    int p = d_off[dst] + atomicAdd(&d_cnt[dst], 1);
    d_csr[p] = src;
}

// ---------------- tf32 tensor-core GEMM -------------------------------------
// C[M,N] = A[M,K] @ B[K,N], row-major. Block tile 128x128, K-tile 32, 3-stage
// cp.async pipeline, one __syncthreads per tile.
// Precision: A split exactly (ah+al, RN tf32); B rounded once (RN tf32).
// acc += ah*bh + al*bh  => error ~ eps_tf32(B) only, zero-mean -> ~1e-4 final.
// Fused epilogue: per-head attention dots (N-tile == one head of 128 ch).
#define A_LD 36    // banks (36*g + c) % 32 = 4g + c -> conflict-free frags
#define B_LD 136   // banks (136*c + g) % 32 = 8c + g -> conflict-free frags
#define STG_FLOATS (128 * A_LD + 32 * B_LD)               // 8960 floats/stage
#define GEMM_SMEM  (3 * STG_FLOATS * (int)sizeof(float))  // 107520 bytes

__device__ __forceinline__ unsigned f2tf32(float v) {
    unsigned r;
    asm("cvt.rna.tf32.f32 %0, %1;\n" : "=r"(r) : "f"(v));
    return r;
}

__device__ __forceinline__ void split_tf32(float v, unsigned& hi, unsigned& lo) {
    hi = f2tf32(v);
    lo = f2tf32(v - __uint_as_float(hi));
}

__device__ __forceinline__ void mma8(float* d, const unsigned* a, const unsigned* b) {
    asm volatile(
        "mma.sync.aligned.m16n8k8.row.col.f32.tf32.tf32.f32 "
        "{%0,%1,%2,%3}, {%4,%5,%6,%7}, {%8,%9}, {%0,%1,%2,%3};\n"
        : "+f"(d[0]), "+f"(d[1]), "+f"(d[2]), "+f"(d[3])
        : "r"(a[0]), "r"(a[1]), "r"(a[2]), "r"(a[3]), "r"(b[0]), "r"(b[1]));
}

__device__ __forceinline__ void cpasync16(void* smem_dst, const void* gsrc, int srcsize) {
    unsigned dst = (unsigned)__cvta_generic_to_shared(smem_dst);
    asm volatile("cp.async.cg.shared.global [%0], [%1], 16, %2;\n"
                 :: "r"(dst), "l"(gsrc), "r"(srcsize));
}

__global__ __launch_bounds__(256)
void gemm_tf32(const float* __restrict__ A, const float* __restrict__ B,
               float* __restrict__ C, int M, int N, int K,
               const float* __restrict__ att_s, const float* __restrict__ att_d,
               float* __restrict__ das, float* __restrict__ dad, int hstride) {
    extern __shared__ float smem[];
    const int tid  = threadIdx.x;
    const int lane = tid & 31;
    const int warp = tid >> 5;
    const int g = lane >> 2;           // 0..7
    const int c = lane & 3;            // 0..3
    const int warpM = (warp & 1) * 64;
    const int warpN = (warp >> 1) * 32;
    const int blockM = blockIdx.y * 128;
    const int blockN = blockIdx.x * 128;

    float acc[4][4][4];
    #pragma unroll
    for (int mt = 0; mt < 4; mt++)
        #pragma unroll
        for (int nt = 0; nt < 4; nt++)
            #pragma unroll
            for (int i = 0; i < 4; i++) acc[mt][nt][i] = 0.f;

    const int T = K >> 5;   // K/32 tiles (24 or 32)

    auto load_stage = [&](int t, int stg) {
        float* sA = smem + stg * STG_FLOATS;
        float* sB = sA + 128 * A_LD;
        const int k0 = t << 5;
        #pragma unroll
        for (int i = 0; i < 4; i++) {
            int linear = i * 256 + tid;
            int r  = linear >> 3;
            int kq = (linear & 7) << 2;
            int gRow = blockM + r;
            cpasync16(&sA[r * A_LD + kq],
                      A + (size_t)gRow * K + k0 + kq,
                      (gRow < M) ? 16 : 0);
        }
        #pragma unroll
        for (int i = 0; i < 4; i++) {
            int linear = i * 256 + tid;
            int kk = linear >> 5;
            int nq = (linear & 31) << 2;
            cpasync16(&sB[kk * B_LD + nq],
                      B + (size_t)(k0 + kk) * N + blockN + nq, 16);
        }
    };

    load_stage(0, 0);
    asm volatile("cp.async.commit_group;\n" ::);
    load_stage(1, 1);
    asm volatile("cp.async.commit_group;\n" ::);

    for (int t = 0; t < T; t++) {
        // pending groups at this point: {t, t+1}; wait until only newest remains
        asm volatile("cp.async.wait_group 1;\n" ::);
        __syncthreads();   // stage t visible to all; prev compute (t-1) finished

        if (t + 2 < T) load_stage(t + 2, (t + 2) % 3);
        asm volatile("cp.async.commit_group;\n" ::);   // empty group ok; keeps count

        const float* sA = smem + (t % 3) * STG_FLOATS;
        const float* sB = sA + 128 * A_LD;

        #pragma unroll
        for (int ks = 0; ks < 4; ks++) {
            const int kb = ks * 8;
            unsigned ah[4][4], al[4][4], bh[4][2];
            #pragma unroll
            for (int mt = 0; mt < 4; mt++) {
                int row = warpM + mt * 16;
                split_tf32(sA[(row + g)     * A_LD + kb + c],     ah[mt][0], al[mt][0]);
                split_tf32(sA[(row + g + 8) * A_LD + kb + c],     ah[mt][1], al[mt][1]);
                split_tf32(sA[(row + g)     * A_LD + kb + c + 4], ah[mt][2], al[mt][2]);
                split_tf32(sA[(row + g + 8) * A_LD + kb + c + 4], ah[mt][3], al[mt][3]);
            }
            #pragma unroll
            for (int nt = 0; nt < 4; nt++) {
                int col = warpN + nt * 8;
                bh[nt][0] = f2tf32(sB[(kb + c)     * B_LD + col + g]);
                bh[nt][1] = f2tf32(sB[(kb + c + 4) * B_LD + col + g]);
            }
            #pragma unroll
            for (int mt = 0; mt < 4; mt++)
                #pragma unroll
                for (int nt = 0; nt < 4; nt++) {
                    mma8(acc[mt][nt], ah[mt], bh[nt]);   // hi * b
                    mma8(acc[mt][nt], al[mt], bh[nt]);   // lo * b
                }
        }
    }

    // ---- fused attention dot-products (N-tile == one head) ----
    if (att_s) {
        float asv[8], adv[8];
        #pragma unroll
        for (int nt = 0; nt < 4; nt++) {
            int colg = blockN + warpN + nt * 8 + 2 * c;
            asv[nt * 2]     = att_s[colg];
            asv[nt * 2 + 1] = att_s[colg + 1];
            adv[nt * 2]     = att_d[colg];
            adv[nt * 2 + 1] = att_d[colg + 1];
        }
        #pragma unroll
        for (int mt = 0; mt < 4; mt++) {
            float s0 = 0.f, d0 = 0.f, s1 = 0.f, d1 = 0.f;
            #pragma unroll
            for (int nt = 0; nt < 4; nt++) {
                s0 += acc[mt][nt][0] * asv[nt * 2] + acc[mt][nt][1] * asv[nt * 2 + 1];
                d0 += acc[mt][nt][0] * adv[nt * 2] + acc[mt][nt][1] * adv[nt * 2 + 1];
                s1 += acc[mt][nt][2] * asv[nt * 2] + acc[mt][nt][3] * asv[nt * 2 + 1];
                d1 += acc[mt][nt][2] * adv[nt * 2] + acc[mt][nt][3] * adv[nt * 2 + 1];
            }
            // reduce over the 4 c-lanes (bits 0-1 of lane)
            #pragma unroll
            for (int o = 1; o <= 2; o <<= 1) {
                s0 += __shfl_xor_sync(0xffffffffu, s0, o);
                d0 += __shfl_xor_sync(0xffffffffu, d0, o);
                s1 += __shfl_xor_sync(0xffffffffu, s1, o);
                d1 += __shfl_xor_sync(0xffffffffu, d1, o);
            }
            if (c == 0) {
                int row0 = blockM + warpM + mt * 16 + g;
                if (row0 < M) {
                    atomicAdd(&das[row0 * hstride + blockIdx.x], s0);
                    atomicAdd(&dad[row0 * hstride + blockIdx.x], d0);
                }
                int row1 = row0 + 8;
                if (row1 < M) {
                    atomicAdd(&das[row1 * hstride + blockIdx.x], s1);
                    atomicAdd(&dad[row1 * hstride + blockIdx.x], d1);
                }
            }
        }
    }

    // ---- store C ----
    #pragma unroll
    for (int mt = 0; mt < 4; mt++)
        #pragma unroll
        for (int nt = 0; nt < 4; nt++) {
            int row0 = blockM + warpM + mt * 16 + g;
            int col  = blockN + warpN + nt * 8 + 2 * c;
            if (row0 < M)
                *(float2*)(C + (size_t)row0 * N + col) =
                    make_float2(acc[mt][nt][0], acc[mt][nt][1]);
            int row1 = row0 + 8;
            if (row1 < M)
                *(float2*)(C + (size_t)row1 * N + col) =
                    make_float2(acc[mt][nt][2], acc[mt][nt][3]);
        }
}

// ---------------- GAT aggregation (CSR per-dst-node, local softmax) --------
__device__ __forceinline__ void sAtomicMaxF(float* a, float v) {
    int* ai = (int*)a;
    int old = *ai;
    while (__int_as_float(old) < v) {
        int assumed = old;
        old = atomicCAS(ai, assumed, __float_as_int(v));
        if (old == assumed) break;
    }
}

__global__ __launch_bounds__(256)
void k_agg1(const float* __restrict__ bias) {
    int n = blockIdx.x;
    int s0 = d_off[n];
    int deg = d_off[n + 1] - s0;
    __shared__ float sm[H1H], sz[H1H], sad[H1H];
    int tid = threadIdx.x;
    if (tid < H1H) { sad[tid] = d_ad1[n * H1H + tid]; sm[tid] = -1e30f; sz[tid] = 0.f; }
    __syncthreads();
    for (int idx = tid; idx < deg * H1H; idx += 256) {
        int e = idx >> 3, hh = idx & 7;
        int src = d_csr[s0 + e];
        float v = d_as1[src * H1H + hh] + sad[hh];
        v = v > 0.f ? v : NEG * v;
        sAtomicMaxF(&sm[hh], v);
    }
    __syncthreads();
    for (int idx = tid; idx < deg * H1H; idx += 256) {
        int e = idx >> 3, hh = idx & 7;
        int src = d_csr[s0 + e];
        float v = d_as1[src * H1H + hh] + sad[hh];
        v = v > 0.f ? v : NEG * v;
        atomicAdd(&sz[hh], __expf(v - sm[hh]));
    }
    __syncthreads();
    int c0 = tid * 4;
    int hh = c0 >> 7;
    float m = sm[hh], invz = 1.f / sz[hh], ad = sad[hh];
    float4 acc = make_float4(0.f, 0.f, 0.f, 0.f);
    for (int e = 0; e < deg; e++) {
        int src = d_csr[s0 + e];
        float v = d_as1[src * H1H + hh] + ad;
        v = v > 0.f ? v : NEG * v;
        float al = __expf(v - m) * invz;
        float4 hv = *(const float4*)(d_h1 + (size_t)src * F1 + c0);
        acc.x += al * hv.x; acc.y += al * hv.y;
        acc.z += al * hv.z; acc.w += al * hv.w;
    }
    float4 bb = *(const float4*)(bias + c0);
    acc.x += bb.x; acc.y += bb.y; acc.z += bb.z; acc.w += bb.w;
    *(float4*)(d_g1 + (size_t)n * F1 + c0) = acc;
}

__global__ __launch_bounds__(128)
void k_agg2(const float* __restrict__ bias) {
    int n = blockIdx.x;
    int s0 = d_off[n];
    int deg = d_off[n + 1] - s0;
    __shared__ float sm, sz, sad;
    int tid = threadIdx.x;
    if (tid == 0) { sad = d_ad2[n]; sm = -1e30f; sz = 0.f; }
    __syncthreads();
    for (int e = tid; e < deg; e += 128) {
        float v = d_as2[d_csr[s0 + e]] + sad;
        v = v > 0.f ? v : NEG * v;
        sAtomicMaxF(&sm, v);
    }
    __syncthreads();
    for (int e = tid; e < deg; e += 128) {
        float v = d_as2[d_csr[s0 + e]] + sad;
        v = v > 0.f ? v : NEG * v;
        atomicAdd(&sz, __expf(v - sm));
    }
    __syncthreads();
    float m = sm, invz = 1.f / sz, ad = sad;
    float acc = 0.f;
    for (int e = 0; e < deg; e++) {
        int src = d_csr[s0 + e];
        float v = d_as2[src] + ad;
        v = v > 0.f ? v : NEG * v;
        acc += __expf(v - m) * invz * d_h2[(size_t)src * F2 + tid];
    }
    d_g2[(size_t)n * F2 + tid] = acc + bias[tid];
}

// ---------------- BatchNorm + ELU ------------------------------------------
__global__ void bn_stats(const float* __restrict__ x, float* __restrict__ sum,
                         float* __restrict__ sq, int F) {
    int col = blockIdx.x * 128 + threadIdx.x;
    float s = 0.f, q = 0.f;
    for (int r = blockIdx.y; r < NN; r += gridDim.y) {
        float v = x[(size_t)r * F + col];
        s += v; q += v * v;
    }
    atomicAdd(&sum[col], s);
    atomicAdd(&sq[col], q);
}

__global__ void bn_final(const float* __restrict__ sum, const float* __restrict__ sq,
                         const float* __restrict__ gamma, const float* __restrict__ beta,
                         float* __restrict__ scale, float* __restrict__ shift, int F) {
    int c = blockIdx.x * blockDim.x + threadIdx.x;
    if (c < F) {
        float mu  = sum[c] * (1.f / NN);
        float var = sq[c] * (1.f / NN) - mu * mu;
        float sc  = gamma[c] * rsqrtf(var + BNEPS);
        scale[c] = sc;
        shift[c] = beta[c] - mu * sc;
    }
}

__global__ void bn_apply_elu(float* __restrict__ x, const float* __restrict__ scale,
                             const float* __restrict__ shift, int mask, int total) {
    int i = blockIdx.x * blockDim.x + threadIdx.x;
    if (i < total) {
        int c = i & mask;
        float v = x[i] * scale[c] + shift[c];
        x[i] = v > 0.f ? v : (__expf(v) - 1.f);
    }
}

// ---------------- classifier head ------------------------------------------
__global__ __launch_bounds__(64)
void k_classifier(const float* __restrict__ g2, const float* __restrict__ Wc1,
                  const float* __restrict__ bc1, const float* __restrict__ Wc2,
                  const float* __restrict__ bc2, float* __restrict__ out) {
    int n = blockIdx.x;
    int tid = threadIdx.x;
    __shared__ float sx[128], sh[64];
    sx[tid]      = g2[(size_t)n * F2 + tid];
    sx[tid + 64] = g2[(size_t)n * F2 + 64 + tid];
    __syncthreads();
    float s = bc1[tid];
    #pragma unroll 8
    for (int k = 0; k < 128; k++) s += sx[k] * Wc1[k * 64 + tid];
    sh[tid] = fmaxf(s, 0.f);
    __syncthreads();
    if (tid < 2) {
        float o = bc2[tid];
        #pragma unroll 8
        for (int k = 0; k < 64; k++) o += sh[k] * Wc2[k * 2 + tid];
        out[n * 2 + tid] = o;
    }
}

// ---------------- launch ----------------------------------------------------
extern "C" void kernel_launch(void* const* d_in, const int* in_sizes, int n_in,
                              void* d_out, int out_size) {
    const float* x     = (const float*)d_in[0];
    const void*  ei    = d_in[1];                 // int32 or int64 — detected on device
    const float* W1    = (const float*)d_in[2];
    const float* atts1 = (const float*)d_in[3];
    const float* attd1 = (const float*)d_in[4];
    const float* b1    = (const float*)d_in[5];
    const float* W2    = (const float*)d_in[6];
    const float* atts2 = (const float*)d_in[7];
    const float* attd2 = (const float*)d_in[8];
    const float* b2    = (const float*)d_in[9];
    const float* g1    = (const float*)d_in[10];
    const float* be1   = (const float*)d_in[11];
    const float* g2w   = (const float*)d_in[12];
    const float* be2   = (const float*)d_in[13];
    const float* Wc1   = (const float*)d_in[14];
    const float* bc1   = (const float*)d_in[15];
    const float* Wc2   = (const float*)d_in[16];
    const float* bc2   = (const float*)d_in[17];
    float*       out   = (float*)d_out;

    void *p_deg, *p_h1, *p_g1, *p_h2, *p_g2, *p_bsum, *p_bsq, *p_scale, *p_shift;
    void *p_as1, *p_ad1, *p_as2, *p_ad2;
    cudaGetSymbolAddress(&p_deg,   d_deg);
    cudaGetSymbolAddress(&p_h1,    d_h1);
    cudaGetSymbolAddress(&p_g1,    d_g1);
    cudaGetSymbolAddress(&p_h2,    d_h2);
    cudaGetSymbolAddress(&p_g2,    d_g2);
    cudaGetSymbolAddress(&p_bsum,  d_bsum);
    cudaGetSymbolAddress(&p_bsq,   d_bsq);
    cudaGetSymbolAddress(&p_scale, d_scale);
    cudaGetSymbolAddress(&p_shift, d_shift);
    cudaGetSymbolAddress(&p_as1,   d_as1);
    cudaGetSymbolAddress(&p_ad1,   d_ad1);
    cudaGetSymbolAddress(&p_as2,   d_as2);
    cudaGetSymbolAddress(&p_ad2,   d_ad2);

    cudaFuncSetAttribute(gemm_tf32, cudaFuncAttributeMaxDynamicSharedMemorySize,
                         GEMM_SMEM);

    // CSR build
    cudaMemsetAsync(p_deg, 0, NN * sizeof(int));
    k_detect<<<1, 32>>>(ei);
    k_count<<<(ETOT + 255) / 256, 256>>>(ei);
    k_scan<<<1, 1024>>>();
    k_scatter<<<(ETOT + 255) / 256, 256>>>(ei);

    // ---- GAT layer 1 (GEMM with fused attention dots) ----
    cudaMemsetAsync(p_as1, 0, NN * H1H * sizeof(float));
    cudaMemsetAsync(p_ad1, 0, NN * H1H * sizeof(float));
    {
        dim3 grid(F1 / 128, (NN + 127) / 128);
        gemm_tf32<<<grid, 256, GEMM_SMEM>>>(x, W1, (float*)p_h1, NN, F1, DIN,
                                            atts1, attd1,
                                            (float*)p_as1, (float*)p_ad1, H1H);
    }
    k_agg1<<<NN, 256>>>(b1);

    // BN1 + ELU (in place on d_g1)
    cudaMemsetAsync(p_bsum, 0, F1 * sizeof(float));
    cudaMemsetAsync(p_bsq,  0, F1 * sizeof(float));
    {
        dim3 grid(F1 / 128, 128);
        bn_stats<<<grid, 128>>>((const float*)p_g1, (float*)p_bsum, (float*)p_bsq, F1);
    }
    bn_final<<<F1 / 128, 128>>>((const float*)p_bsum, (const float*)p_bsq, g1, be1,
                                (float*)p_scale, (float*)p_shift, F1);
    bn_apply_elu<<<(NN * F1 + 255) / 256, 256>>>((float*)p_g1, (const float*)p_scale,
                                                 (const float*)p_shift, F1 - 1, NN * F1);

    // ---- GAT layer 2 (GEMM with fused attention dots) ----
    cudaMemsetAsync(p_as2, 0, NN * sizeof(float));
    cudaMemsetAsync(p_ad2, 0, NN * sizeof(float));
    {
        dim3 grid(F2 / 128, (NN + 127) / 128);
        gemm_tf32<<<grid, 256, GEMM_SMEM>>>((const float*)p_g1, W2, (float*)p_h2,
                                            NN, F2, F1,
                                            atts2, attd2,
                                            (float*)p_as2, (float*)p_ad2, 1);
    }
    k_agg2<<<NN, 128>>>(b2);

    // BN2 + ELU (in place on d_g2)
    cudaMemsetAsync(p_bsum, 0, F2 * sizeof(float));
    cudaMemsetAsync(p_bsq,  0, F2 * sizeof(float));
    {
        dim3 grid(F2 / 128, 128);
        bn_stats<<<grid, 128>>>((const float*)p_g2, (float*)p_bsum, (float*)p_bsq, F2);
    }
    bn_final<<<1, 128>>>((const float*)p_bsum, (const float*)p_bsq, g2w, be2,
                         (float*)p_scale, (float*)p_shift, F2);
    bn_apply_elu<<<(NN * F2 + 255) / 256, 256>>>((float*)p_g2, (const float*)p_scale,
                                                 (const float*)p_shift, F2 - 1, NN * F2);

    // ---- classifier head ----
    k_classifier<<<NN, 64>>>((const float*)p_g2, Wc1, bc1, Wc2, bc2, out);
}

// round 8
// speedup vs baseline: 1.6278x; 1.0217x over previous
#include <cuda_runtime.h>

// Problem constants (fixed shapes)
#define NN   20000
#define EE   320000
#define ETOT 340000      // EE + NN self-loops
#define DIN  768
#define F1   1024        // H1*C1
#define H1H  8
#define C1C  128
#define F2   128
#define NEG  0.2f
#define BNEPS 1e-5f

// ---------------- scratch (device globals; no allocation allowed) ----------
__device__ float d_h1[NN * F1];
__device__ float d_g1[NN * F1];
__device__ float d_h2[NN * F2];
__device__ float d_g2[NN * F2];
__device__ float d_as1[NN * H1H];
__device__ float d_ad1[NN * H1H];
__device__ float d_as2[NN];
__device__ float d_ad2[NN];
__device__ int   d_deg[NN];
__device__ int   d_off[NN + 1];
__device__ int   d_cnt[NN];
__device__ int   d_csr[ETOT];
__device__ float d_bsum[F1];
__device__ float d_bsq[F1];
__device__ float d_scale[F1];
__device__ float d_shift[F1];
__device__ int   d_is64;

// ---------------- dtype detection (parallel) --------------------------------
__global__ void k_detect(const void* ei) {
    __shared__ int ok;
    int t = threadIdx.x;
    if (t == 0) ok = 1;
    __syncthreads();
    long long v = ((const long long*)ei)[t];
    if (v < 0 || v >= NN) ok = 0;       // benign race, any writer suffices
    __syncthreads();
    if (t == 0) d_is64 = ok;
}

__device__ __forceinline__ int load_idx(const void* ei, int i) {
    int v = d_is64 ? (int)((const long long*)ei)[i] : ((const int*)ei)[i];
    v = v < 0 ? 0 : (v >= NN ? NN - 1 : v);
    return v;
}

// ---------------- CSR build ------------------------------------------------
__global__ void k_count(const void* __restrict__ ei) {
    int i = blockIdx.x * blockDim.x + threadIdx.x;
    if (i >= ETOT) return;
    int dst = (i < EE) ? load_idx(ei, EE + i) : (i - EE);
    atomicAdd(&d_deg[dst], 1);
}

__global__ void k_scan() {   // single block, 1024 threads
    __shared__ int s[1024];
    __shared__ int carry;
    int tid = threadIdx.x;
    if (tid == 0) { carry = 0; d_off[0] = 0; }
    __syncthreads();
    for (int base = 0; base < NN; base += 1024) {
        int i = base + tid;
        int v = (i < NN) ? d_deg[i] : 0;
        s[tid] = v;
        __syncthreads();
        #pragma unroll
        for (int ofs = 1; ofs < 1024; ofs <<= 1) {
            int t = (tid >= ofs) ? s[tid - ofs] : 0;
            __syncthreads();
            s[tid] += t;
            __syncthreads();
        }
        if (i < NN) d_off[i + 1] = carry + s[tid];
        __syncthreads();
        if (tid == 0) carry += s[1023];
        __syncthreads();
    }
    // zero scratch consumed later in the stream (saves memset launches)
    for (int i = tid; i < NN; i += 1024) d_cnt[i] = 0;
    for (int i = tid; i < NN * H1H; i += 1024) { d_as1[i] = 0.f; d_ad1[i] = 0.f; }
    for (int i = tid; i < NN; i += 1024) { d_as2[i] = 0.f; d_ad2[i] = 0.f; }
}

__global__ void k_scatter(const void* __restrict__ ei) {
    int i = blockIdx.x * blockDim.x + threadIdx.x;
    if (i >= ETOT) return;
    int src, dst;
    if (i < EE) { src = load_idx(ei, i); dst = load_idx(ei, EE + i); }
    else        { src = dst = i - EE; }
    int p = d_off[dst] + atomicAdd(&d_cnt[dst], 1);
    d_csr[p] = src;
}

// ---------------- bf16 3-pass tensor-core GEMM ------------------------------
// C[M,N] = A[M,K] @ B[K,N], row-major. Block tile 128x128, K-tile 32, 3-stage
// cp.async pipeline. Both operands split exactly into (hi+lo) bf16 pairs;
// acc += ah*bh + ah*bl + al*bh  -> per-element error ~2^-18 (drops al*bl).
// Optional fused BN+ELU transform on A load (for layer-2 GEMM) and fused
// per-head attention dot-products in the epilogue.
#define A_LD 40    // float2 LDS: bank pair (8g+2c) distinct per half-warp phase
#define B_LD 132   // scalar LDS: bank (8c+g+4delta) distinct per instruction
#define STG_FLOATS (128 * A_LD + 32 * B_LD)               // 9344 floats/stage
#define GEMM_SMEM  (3 * STG_FLOATS * (int)sizeof(float))  // 112128 bytes

// pack two floats into bf16x2 (fhi -> high half, flo -> low half), RN
__device__ __forceinline__ unsigned packbf(float fhi, float flo) {
    unsigned r;
    asm("cvt.rn.bf16x2.f32 %0, %1, %2;\n" : "=r"(r) : "f"(fhi), "f"(flo));
    return r;
}

// exact 2-term bf16 split of a float pair (flo = k-even elt, fhi = k-odd elt)
__device__ __forceinline__ void split2(float fhi, float flo,
                                       unsigned& h, unsigned& l) {
    h = packbf(fhi, flo);
    float rh = __uint_as_float(h & 0xffff0000u);
    float rl = __uint_as_float(h << 16);
    l = packbf(fhi - rh, flo - rl);
}

__device__ __forceinline__ void mma16(float* d, const unsigned* a, const unsigned* b) {
    asm volatile(
        "mma.sync.aligned.m16n8k16.row.col.f32.bf16.bf16.f32 "
        "{%0,%1,%2,%3}, {%4,%5,%6,%7}, {%8,%9}, {%0,%1,%2,%3};\n"
        : "+f"(d[0]), "+f"(d[1]), "+f"(d[2]), "+f"(d[3])
        : "r"(a[0]), "r"(a[1]), "r"(a[2]), "r"(a[3]), "r"(b[0]), "r"(b[1]));
}

__device__ __forceinline__ void cpasync16(void* smem_dst, const void* gsrc, int srcsize) {
    unsigned dst = (unsigned)__cvta_generic_to_shared(smem_dst);
    asm volatile("cp.async.cg.shared.global [%0], [%1], 16, %2;\n"
                 :: "r"(dst), "l"(gsrc), "r"(srcsize));
}

__device__ __forceinline__ float eluf(float v) {
    return v > 0.f ? v : (__expf(v) - 1.f);
}

__global__ __launch_bounds__(256)
void gemm_bf16(const float* __restrict__ A, const float* __restrict__ B,
               float* __restrict__ C, int M, int N, int K,
               const float* __restrict__ att_s, const float* __restrict__ att_d,
               float* __restrict__ das, float* __restrict__ dad, int hstride,
               const float* __restrict__ bnscale, const float* __restrict__ bnshift) {
    extern __shared__ float smem[];
    const int tid  = threadIdx.x;
    const int lane = tid & 31;
    const int warp = tid >> 5;
    const int g = lane >> 2;           // 0..7
    const int c = lane & 3;            // 0..3
    const int warpM = (warp & 1) * 64;
    const int warpN = (warp >> 1) * 32;
    const int blockM = blockIdx.y * 128;
    const int blockN = blockIdx.x * 128;

    float acc[4][4][4];
    #pragma unroll
    for (int mt = 0; mt < 4; mt++)
        #pragma unroll
        for (int nt = 0; nt < 4; nt++)
            #pragma unroll
            for (int i = 0; i < 4; i++) acc[mt][nt][i] = 0.f;

    const int T = K >> 5;

    auto load_stage = [&](int t, int stg) {
        float* sA = smem + stg * STG_FLOATS;
        float* sB = sA + 128 * A_LD;
        const int k0 = t << 5;
        if (bnscale) {
            // fused BN+ELU transform on A (layer-2 GEMM): LDG -> xform -> STS
            #pragma unroll
            for (int i = 0; i < 4; i++) {
                int linear = i * 256 + tid;
                int r  = linear >> 3;
                int kq = (linear & 7) << 2;
                int gRow = blockM + r;
                float4 v = make_float4(0.f, 0.f, 0.f, 0.f);
                if (gRow < M) v = *(const float4*)(A + (size_t)gRow * K + k0 + kq);
                float4 sc = *(const float4*)(bnscale + k0 + kq);
                float4 sh = *(const float4*)(bnshift + k0 + kq);
                v.x = eluf(v.x * sc.x + sh.x);
                v.y = eluf(v.y * sc.y + sh.y);
                v.z = eluf(v.z * sc.z + sh.z);
                v.w = eluf(v.w * sc.w + sh.w);
                *(float4*)&sA[r * A_LD + kq] = v;
            }
        } else {
            #pragma unroll
            for (int i = 0; i < 4; i++) {
                int linear = i * 256 + tid;
                int r  = linear >> 3;
                int kq = (linear & 7) << 2;
                int gRow = blockM + r;
                cpasync16(&sA[r * A_LD + kq],
                          A + (size_t)gRow * K + k0 + kq,
                          (gRow < M) ? 16 : 0);
            }
        }
        #pragma unroll
        for (int i = 0; i < 4; i++) {
            int linear = i * 256 + tid;
            int kk = linear >> 5;
            int nq = (linear & 31) << 2;
            cpasync16(&sB[kk * B_LD + nq],
                      B + (size_t)(k0 + kk) * N + blockN + nq, 16);
        }
    };

    load_stage(0, 0);
    asm volatile("cp.async.commit_group;\n" ::);
    load_stage(1, 1);
    asm volatile("cp.async.commit_group;\n" ::);

    for (int t = 0; t < T; t++) {
        asm volatile("cp.async.wait_group 1;\n" ::);
        __syncthreads();

        if (t + 2 < T) load_stage(t + 2, (t + 2) % 3);
        asm volatile("cp.async.commit_group;\n" ::);

        const float* sA = smem + (t % 3) * STG_FLOATS;
        const float* sB = sA + 128 * A_LD;

        #pragma unroll
        for (int ks = 0; ks < 2; ks++) {
            const int kb = ks * 16;
            unsigned ah[4][4], al[4][4];
            #pragma unroll
            for (int mt = 0; mt < 4; mt++) {
                int r0 = warpM + mt * 16 + g;
                int r1 = r0 + 8;
                float2 v00 = *(const float2*)&sA[r0 * A_LD + kb + 2 * c];
                float2 v10 = *(const float2*)&sA[r1 * A_LD + kb + 2 * c];
                float2 v01 = *(const float2*)&sA[r0 * A_LD + kb + 8 + 2 * c];
                float2 v11 = *(const float2*)&sA[r1 * A_LD + kb + 8 + 2 * c];
                split2(v00.y, v00.x, ah[mt][0], al[mt][0]);
                split2(v10.y, v10.x, ah[mt][1], al[mt][1]);
                split2(v01.y, v01.x, ah[mt][2], al[mt][2]);
                split2(v11.y, v11.x, ah[mt][3], al[mt][3]);
            }
            #pragma unroll
            for (int nt = 0; nt < 4; nt++) {
                int col = warpN + nt * 8 + g;
                float b00 = sB[(kb + 2 * c)     * B_LD + col];
                float b01 = sB[(kb + 2 * c + 1) * B_LD + col];
                float b10 = sB[(kb + 2 * c + 8) * B_LD + col];
                float b11 = sB[(kb + 2 * c + 9) * B_LD + col];
                unsigned bh[2], bl[2];
                split2(b01, b00, bh[0], bl[0]);
                split2(b11, b10, bh[1], bl[1]);
                #pragma unroll
                for (int mt = 0; mt < 4; mt++) {
                    mma16(acc[mt][nt], ah[mt], bh);   // hi*hi
                    mma16(acc[mt][nt], ah[mt], bl);   // hi*lo
                    mma16(acc[mt][nt], al[mt], bh);   // lo*hi
                }
            }
        }
    }

    // ---- fused attention dot-products (N-tile == one head) ----
    if (att_s) {
        float asv[8], adv[8];
        #pragma unroll
        for (int nt = 0; nt < 4; nt++) {
            int colg = blockN + warpN + nt * 8 + 2 * c;
            asv[nt * 2]     = att_s[colg];
            asv[nt * 2 + 1] = att_s[colg + 1];
            adv[nt * 2]     = att_d[colg];
            adv[nt * 2 + 1] = att_d[colg + 1];
        }
        #pragma unroll
        for (int mt = 0; mt < 4; mt++) {
            float s0 = 0.f, d0 = 0.f, s1 = 0.f, d1 = 0.f;
            #pragma unroll
            for (int nt = 0; nt < 4; nt++) {
                s0 += acc[mt][nt][0] * asv[nt * 2] + acc[mt][nt][1] * asv[nt * 2 + 1];
                d0 += acc[mt][nt][0] * adv[nt * 2] + acc[mt][nt][1] * adv[nt * 2 + 1];
                s1 += acc[mt][nt][2] * asv[nt * 2] + acc[mt][nt][3] * asv[nt * 2 + 1];
                d1 += acc[mt][nt][2] * adv[nt * 2] + acc[mt][nt][3] * adv[nt * 2 + 1];
            }
            #pragma unroll
            for (int o = 1; o <= 2; o <<= 1) {
                s0 += __shfl_xor_sync(0xffffffffu, s0, o);
                d0 += __shfl_xor_sync(0xffffffffu, d0, o);
                s1 += __shfl_xor_sync(0xffffffffu, s1, o);
                d1 += __shfl_xor_sync(0xffffffffu, d1, o);
            }
            if (c == 0) {
                int row0 = blockM + warpM + mt * 16 + g;
                if (row0 < M) {
                    atomicAdd(&das[row0 * hstride + blockIdx.x], s0);
                    atomicAdd(&dad[row0 * hstride + blockIdx.x], d0);
                }
                int row1 = row0 + 8;
                if (row1 < M) {
                    atomicAdd(&das[row1 * hstride + blockIdx.x], s1);
                    atomicAdd(&dad[row1 * hstride + blockIdx.x], d1);
                }
            }
        }
    }

    // ---- store C ----
    #pragma unroll
    for (int mt = 0; mt < 4; mt++)
        #pragma unroll
        for (int nt = 0; nt < 4; nt++) {
            int row0 = blockM + warpM + mt * 16 + g;
            int col  = blockN + warpN + nt * 8 + 2 * c;
            if (row0 < M)
                *(float2*)(C + (size_t)row0 * N + col) =
                    make_float2(acc[mt][nt][0], acc[mt][nt][1]);
            int row1 = row0 + 8;
            if (row1 < M)
                *(float2*)(C + (size_t)row1 * N + col) =
                    make_float2(acc[mt][nt][2], acc[mt][nt][3]);
        }
}

// ---------------- GAT aggregation (CSR per-dst-node, local softmax) --------
__device__ __forceinline__ void sAtomicMaxF(float* a, float v) {
    int* ai = (int*)a;
    int old = *ai;
    while (__int_as_float(old) < v) {
        int assumed = old;
        old = atomicCAS(ai, assumed, __float_as_int(v));
        if (old == assumed) break;
    }
}

__global__ __launch_bounds__(256)
void k_agg1(const float* __restrict__ bias) {
    int n = blockIdx.x;
    int s0 = d_off[n];
    int deg = d_off[n + 1] - s0;
    __shared__ float sm[H1H], sz[H1H], sad[H1H];
    int tid = threadIdx.x;
    if (tid < H1H) { sad[tid] = d_ad1[n * H1H + tid]; sm[tid] = -1e30f; sz[tid] = 0.f; }
    __syncthreads();
    for (int idx = tid; idx < deg * H1H; idx += 256) {
        int e = idx >> 3, hh = idx & 7;
        int src = d_csr[s0 + e];
        float v = d_as1[src * H1H + hh] + sad[hh];
        v = v > 0.f ? v : NEG * v;
        sAtomicMaxF(&sm[hh], v);
    }
    __syncthreads();
    for (int idx = tid; idx < deg * H1H; idx += 256) {
        int e = idx >> 3, hh = idx & 7;
        int src = d_csr[s0 + e];
        float v = d_as1[src * H1H + hh] + sad[hh];
        v = v > 0.f ? v : NEG * v;
        atomicAdd(&sz[hh], __expf(v - sm[hh]));
    }
    __syncthreads();
    int c0 = tid * 4;
    int hh = c0 >> 7;
    float m = sm[hh], invz = 1.f / sz[hh], ad = sad[hh];
    float4 acc = make_float4(0.f, 0.f, 0.f, 0.f);
    for (int e = 0; e < deg; e++) {
        int src = d_csr[s0 + e];
        float v = d_as1[src * H1H + hh] + ad;
        v = v > 0.f ? v : NEG * v;
        float al = __expf(v - m) * invz;
        float4 hv = *(const float4*)(d_h1 + (size_t)src * F1 + c0);
        acc.x += al * hv.x; acc.y += al * hv.y;
        acc.z += al * hv.z; acc.w += al * hv.w;
    }
    float4 bb = *(const float4*)(bias + c0);
    acc.x += bb.x; acc.y += bb.y; acc.z += bb.z; acc.w += bb.w;
    *(float4*)(d_g1 + (size_t)n * F1 + c0) = acc;
}

__global__ __launch_bounds__(128)
void k_agg2(const float* __restrict__ bias) {
    int n = blockIdx.x;
    int s0 = d_off[n];
    int deg = d_off[n + 1] - s0;
    __shared__ float sm, sz, sad;
    int tid = threadIdx.x;
    if (tid == 0) { sad = d_ad2[n]; sm = -1e30f; sz = 0.f; }
    __syncthreads();
    for (int e = tid; e < deg; e += 128) {
        float v = d_as2[d_csr[s0 + e]] + sad;
        v = v > 0.f ? v : NEG * v;
        sAtomicMaxF(&sm, v);
    }
    __syncthreads();
    for (int e = tid; e < deg; e += 128) {
        float v = d_as2[d_csr[s0 + e]] + sad;
        v = v > 0.f ? v : NEG * v;
        atomicAdd(&sz, __expf(v - sm));
    }
    __syncthreads();
    float m = sm, invz = 1.f / sz, ad = sad;
    float acc = 0.f;
    for (int e = 0; e < deg; e++) {
        int src = d_csr[s0 + e];
        float v = d_as2[src] + ad;
        v = v > 0.f ? v : NEG * v;
        acc += __expf(v - m) * invz * d_h2[(size_t)src * F2 + tid];
    }
    d_g2[(size_t)n * F2 + tid] = acc + bias[tid];
}

// ---------------- BatchNorm ------------------------------------------------
__global__ void bn_stats(const float* __restrict__ x, float* __restrict__ sum,
                         float* __restrict__ sq, int F) {
    int col = blockIdx.x * 128 + threadIdx.x;
    float s = 0.f, q = 0.f;
    for (int r = blockIdx.y; r < NN; r += gridDim.y) {
        float v = x[(size_t)r * F + col];
        s += v; q += v * v;
    }
    atomicAdd(&sum[col], s);
    atomicAdd(&sq[col], q);
}

__global__ void bn_final(const float* __restrict__ sum, const float* __restrict__ sq,
                         const float* __restrict__ gamma, const float* __restrict__ beta,
                         float* __restrict__ scale, float* __restrict__ shift, int F) {
    int c = blockIdx.x * blockDim.x + threadIdx.x;
    if (c < F) {
        float mu  = sum[c] * (1.f / NN);
        float var = sq[c] * (1.f / NN) - mu * mu;
        float sc  = gamma[c] * rsqrtf(var + BNEPS);
        scale[c] = sc;
        shift[c] = beta[c] - mu * sc;
    }
}

// ---------------- classifier head (fused BN2+ELU) ---------------------------
__global__ __launch_bounds__(64)
void k_classifier(const float* __restrict__ g2, const float* __restrict__ scale,
                  const float* __restrict__ shift,
                  const float* __restrict__ Wc1, const float* __restrict__ bc1,
                  const float* __restrict__ Wc2, const float* __restrict__ bc2,
                  float* __restrict__ out) {
    int n = blockIdx.x;
    int tid = threadIdx.x;
    __shared__ float sx[128], sh[64];
    float v0 = g2[(size_t)n * F2 + tid]      * scale[tid]      + shift[tid];
    float v1 = g2[(size_t)n * F2 + 64 + tid] * scale[tid + 64] + shift[tid + 64];
    sx[tid]      = eluf(v0);
    sx[tid + 64] = eluf(v1);
    __syncthreads();
    float s = bc1[tid];
    #pragma unroll 8
    for (int k = 0; k < 128; k++) s += sx[k] * Wc1[k * 64 + tid];
    sh[tid] = fmaxf(s, 0.f);
    __syncthreads();
    if (tid < 2) {
        float o = bc2[tid];
        #pragma unroll 8
        for (int k = 0; k < 64; k++) o += sh[k] * Wc2[k * 2 + tid];
        out[n * 2 + tid] = o;
    }
}

// ---------------- launch ----------------------------------------------------
extern "C" void kernel_launch(void* const* d_in, const int* in_sizes, int n_in,
                              void* d_out, int out_size) {
    const float* x     = (const float*)d_in[0];
    const void*  ei    = d_in[1];
    const float* W1    = (const float*)d_in[2];
    const float* atts1 = (const float*)d_in[3];
    const float* attd1 = (const float*)d_in[4];
    const float* b1    = (const float*)d_in[5];
    const float* W2    = (const float*)d_in[6];
    const float* atts2 = (const float*)d_in[7];
    const float* attd2 = (const float*)d_in[8];
    const float* b2    = (const float*)d_in[9];
    const float* g1    = (const float*)d_in[10];
    const float* be1   = (const float*)d_in[11];
    const float* g2w   = (const float*)d_in[12];
    const float* be2   = (const float*)d_in[13];
    const float* Wc1   = (const float*)d_in[14];
    const float* bc1   = (const float*)d_in[15];
    const float* Wc2   = (const float*)d_in[16];
    const float* bc2   = (const float*)d_in[17];
    float*       out   = (float*)d_out;

    void *p_deg, *p_h1, *p_g1, *p_h2, *p_g2, *p_bsum, *p_bsq, *p_scale, *p_shift;
    void *p_as1, *p_ad1, *p_as2, *p_ad2;
    cudaGetSymbolAddress(&p_deg,   d_deg);
    cudaGetSymbolAddress(&p_h1,    d_h1);
    cudaGetSymbolAddress(&p_g1,    d_g1);
    cudaGetSymbolAddress(&p_h2,    d_h2);
    cudaGetSymbolAddress(&p_g2,    d_g2);
    cudaGetSymbolAddress(&p_bsum,  d_bsum);
    cudaGetSymbolAddress(&p_bsq,   d_bsq);
    cudaGetSymbolAddress(&p_scale, d_scale);
    cudaGetSymbolAddress(&p_shift, d_shift);
    cudaGetSymbolAddress(&p_as1,   d_as1);
    cudaGetSymbolAddress(&p_ad1,   d_ad1);
    cudaGetSymbolAddress(&p_as2,   d_as2);
    cudaGetSymbolAddress(&p_ad2,   d_ad2);

    cudaFuncSetAttribute(gemm_bf16, cudaFuncAttributeMaxDynamicSharedMemorySize,
                         GEMM_SMEM);

    // CSR build (k_scan also zeros cnt + attention accumulators)
    cudaMemsetAsync(p_deg, 0, NN * sizeof(int));
    k_detect<<<1, 64>>>(ei);
    k_count<<<(ETOT + 255) / 256, 256>>>(ei);
    k_scan<<<1, 1024>>>();
    k_scatter<<<(ETOT + 255) / 256, 256>>>(ei);

    // ---- GAT layer 1: GEMM (fused attention dots) ----
    {
        dim3 grid(F1 / 128, (NN + 127) / 128);
        gemm_bf16<<<grid, 256, GEMM_SMEM>>>(x, W1, (float*)p_h1, NN, F1, DIN,
                                            atts1, attd1,
                                            (float*)p_as1, (float*)p_ad1, H1H,
                                            nullptr, nullptr);
    }
    k_agg1<<<NN, 256>>>(b1);

    // BN1 stats (apply is fused into gemm2's A load)
    cudaMemsetAsync(p_bsum, 0, F1 * sizeof(float));
    cudaMemsetAsync(p_bsq,  0, F1 * sizeof(float));
    {
        dim3 grid(F1 / 128, 128);
        bn_stats<<<grid, 128>>>((const float*)p_g1, (float*)p_bsum, (float*)p_bsq, F1);
    }
    bn_final<<<F1 / 128, 128>>>((const float*)p_bsum, (const float*)p_bsq, g1, be1,
                                (float*)p_scale, (float*)p_shift, F1);

    // ---- GAT layer 2: GEMM (fused BN1+ELU on A, fused attention dots) ----
    {
        dim3 grid(F2 / 128, (NN + 127) / 128);
        gemm_bf16<<<grid, 256, GEMM_SMEM>>>((const float*)p_g1, W2, (float*)p_h2,
                                            NN, F2, F1,
                                            atts2, attd2,
                                            (float*)p_as2, (float*)p_ad2, 1,
                                            (const float*)p_scale,
                                            (const float*)p_shift);
    }
    k_agg2<<<NN, 128>>>(b2);

    // BN2 stats (apply is fused into classifier)
    cudaMemsetAsync(p_bsum, 0, F2 * sizeof(float));
    cudaMemsetAsync(p_bsq,  0, F2 * sizeof(float));
    {
        dim3 grid(F2 / 128, 128);
        bn_stats<<<grid, 128>>>((const float*)p_g2, (float*)p_bsum, (float*)p_bsq, F2);
    }
    bn_final<<<1, 128>>>((const float*)p_bsum, (const float*)p_bsq, g2w, be2,
                         (float*)p_scale, (float*)p_shift, F2);

    // ---- classifier head (fused BN2+ELU) ----
    k_classifier<<<NN, 64>>>((const float*)p_g2, (const float*)p_scale,
                             (const float*)p_shift, Wc1, bc1, Wc2, bc2, out);
}

// round 9
// speedup vs baseline: 1.7261x; 1.0604x over previous
#include <cuda_runtime.h>
#include <cuda_bf16.h>

// Problem constants (fixed shapes)
#define NN   20000
#define EE   320000
#define ETOT 340000      // EE + NN self-loops
#define DIN  768
#define F1   1024        // H1*C1
#define H1H  8
#define C1C  128
#define F2   128
#define NEG  0.2f
#define BNEPS 1e-5f

#define K1P  (3 * DIN)   // 2304  triple-split K for GEMM1
#define K2P  (3 * F1)    // 3072  triple-split K for GEMM2

// ---------------- scratch (device globals; no allocation allowed) ----------
__device__ float d_h1[NN * F1];
__device__ float d_g1[NN * F1];
__device__ float d_h2[NN * F2];
__device__ float d_g2[NN * F2];
__device__ float d_as1[NN * H1H];
__device__ float d_ad1[NN * H1H];
__device__ float d_as2[NN];
__device__ float d_ad2[NN];
__device__ int   d_deg[NN];
__device__ int   d_off[NN + 1];
__device__ int   d_cnt[NN];
__device__ int   d_csr[ETOT];
__device__ float d_bsum[F1];
__device__ float d_bsq[F1];
__device__ float d_scale[F1];
__device__ float d_shift[F1];
__device__ int   d_is64;
// split-bf16 operands (words = bf16x2, k-pair packed: low=even k, high=odd k)
__device__ unsigned d_xs [NN * (K1P / 2)];        // A' for GEMM1, row-major
__device__ unsigned d_g1s[NN * (K2P / 2)];        // A' for GEMM2, row-major
__device__ unsigned d_w1s[(K1P / 2) * F1];        // B' pair-interleaved [k/2][n]
__device__ unsigned d_w2s[(K2P / 2) * F2];

// ---------------- bf16 helpers ----------------------------------------------
__device__ __forceinline__ unsigned packbf(float fhi, float flo) {
    unsigned r;
    asm("cvt.rn.bf16x2.f32 %0, %1, %2;\n" : "=r"(r) : "f"(fhi), "f"(flo));
    return r;
}
__device__ __forceinline__ float bfhi(float v) {   // RN bf16 of v, as float
    unsigned r = packbf(v, v);
    return __uint_as_float(r & 0xffff0000u);
}
__device__ __forceinline__ float eluf(float v) {
    return v > 0.f ? v : (__expf(v) - 1.f);
}

// ---------------- dtype detection (parallel) --------------------------------
__global__ void k_detect(const void* ei) {
    __shared__ int ok;
    int t = threadIdx.x;
    if (t == 0) ok = 1;
    __syncthreads();
    long long v = ((const long long*)ei)[t];
    if (v < 0 || v >= NN) ok = 0;
    __syncthreads();
    if (t == 0) d_is64 = ok;
}

__device__ __forceinline__ int load_idx(const void* ei, int i) {
    int v = d_is64 ? (int)((const long long*)ei)[i] : ((const int*)ei)[i];
    v = v < 0 ? 0 : (v >= NN ? NN - 1 : v);
    return v;
}

// ---------------- CSR build ------------------------------------------------
__global__ void k_count(const void* __restrict__ ei) {
    int i = blockIdx.x * blockDim.x + threadIdx.x;
    if (i >= ETOT) return;
    int dst = (i < EE) ? load_idx(ei, EE + i) : (i - EE);
    atomicAdd(&d_deg[dst], 1);
}

__global__ void k_scan() {
    __shared__ int s[1024];
    __shared__ int carry;
    int tid = threadIdx.x;
    if (tid == 0) { carry = 0; d_off[0] = 0; }
    __syncthreads();
    for (int base = 0; base < NN; base += 1024) {
        int i = base + tid;
        int v = (i < NN) ? d_deg[i] : 0;
        s[tid] = v;
        __syncthreads();
        #pragma unroll
        for (int ofs = 1; ofs < 1024; ofs <<= 1) {
            int t = (tid >= ofs) ? s[tid - ofs] : 0;
            __syncthreads();
            s[tid] += t;
            __syncthreads();
        }
        if (i < NN) d_off[i + 1] = carry + s[tid];
        __syncthreads();
        if (tid == 0) carry += s[1023];
        __syncthreads();
    }
    for (int i = tid; i < NN; i += 1024) d_cnt[i] = 0;
    for (int i = tid; i < NN * H1H; i += 1024) { d_as1[i] = 0.f; d_ad1[i] = 0.f; }
    for (int i = tid; i < NN; i += 1024) { d_as2[i] = 0.f; d_ad2[i] = 0.f; }
}

__global__ void k_scatter(const void* __restrict__ ei) {
    int i = blockIdx.x * blockDim.x + threadIdx.x;
    if (i >= ETOT) return;
    int src, dst;
    if (i < EE) { src = load_idx(ei, i); dst = load_idx(ei, EE + i); }
    else        { src = dst = i - EE; }
    int p = d_off[dst] + atomicAdd(&d_cnt[dst], 1);
    d_csr[p] = src;
}

// ---------------- conversion passes -----------------------------------------
// A' row layout (words per row = 3K/2): [hi(K/2) | lo(K/2) | hi(K/2)]
__global__ void conv_x(const float* __restrict__ X) {
    int idx = blockIdx.x * blockDim.x + threadIdx.x;     // (r, kp) kp in [0,384)
    if (idx >= NN * (DIN / 2)) return;
    int r = idx / (DIN / 2), kp = idx % (DIN / 2);
    float2 v = *(const float2*)(X + (size_t)r * DIN + 2 * kp);
    float h0 = bfhi(v.x), h1 = bfhi(v.y);
    unsigned hp = packbf(h1, h0);
    unsigned lp = packbf(v.y - h1, v.x - h0);
    unsigned* row = d_xs + (size_t)r * (K1P / 2);
    row[kp] = hp;
    row[DIN / 2 + kp] = lp;
    row[DIN + kp] = hp;
}

// g1 -> BN1+ELU -> split triple (fused apply)
__global__ void conv_g1(const float* __restrict__ scale,
                        const float* __restrict__ shift) {
    int idx = blockIdx.x * blockDim.x + threadIdx.x;     // (r, kp) kp in [0,512)
    if (idx >= NN * (F1 / 2)) return;
    int r = idx / (F1 / 2), kp = idx % (F1 / 2);
    float2 v = *(const float2*)(d_g1 + (size_t)r * F1 + 2 * kp);
    float2 sc = *(const float2*)(scale + 2 * kp);
    float2 sh = *(const float2*)(shift + 2 * kp);
    float a0 = eluf(v.x * sc.x + sh.x);
    float a1 = eluf(v.y * sc.y + sh.y);
    float h0 = bfhi(a0), h1 = bfhi(a1);
    unsigned hp = packbf(h1, h0);
    unsigned lp = packbf(a1 - h1, a0 - h0);
    unsigned* row = d_g1s + (size_t)r * (K2P / 2);
    row[kp] = hp;
    row[F1 / 2 + kp] = lp;
    row[F1 + kp] = hp;
}

// W [K][N] fp32 -> W' pair-interleaved [3K/2][N] words: segs [hi | hi | lo]
__global__ void conv_w(const float* __restrict__ W, unsigned* __restrict__ Wp,
                       int K, int N) {
    int idx = blockIdx.x * blockDim.x + threadIdx.x;     // (p, n)
    int tot = (3 * K / 2) * N;
    if (idx >= tot) return;
    int p = idx / N, n = idx % N;
    int k2 = 2 * p;
    int k; bool lo;
    if (k2 < K)          { k = k2;         lo = false; }
    else if (k2 < 2 * K) { k = k2 - K;     lo = false; }
    else                 { k = k2 - 2 * K; lo = true;  }
    float v0 = W[(size_t)k * N + n];
    float v1 = W[(size_t)(k + 1) * N + n];
    unsigned r;
    if (!lo) r = packbf(bfhi(v1), bfhi(v0));
    else     r = packbf(v1 - bfhi(v1), v0 - bfhi(v0));
    Wp[(size_t)p * N + n] = r;
}

// ---------------- split-bf16 tensor-core GEMM -------------------------------
// C[M,N] = A'[M,Kb] @ B'[Kb,N] (bf16, Kb = 3K), row-major A', pair-interleaved
// B'. Block tile 128x128, K-tile 64 bf16, 3-stage cp.async. No conversion ALU
// in the loop. Fused per-head attention dots in the epilogue.
#define A_PITCH_W 36     // A row pitch in 32-bit words (72 bf16); banks 4g+c
#define B_PITCH_W 136    // B pair-row pitch in words; banks 8c+g
#define A_STG_W   (128 * A_PITCH_W)                       // 4608 words
#define B_STG_W   (32 * B_PITCH_W)                        // 4352 words
#define STG_W     (A_STG_W + B_STG_W)                     // 8960 words
#define GEMM_SMEM (3 * STG_W * 4)                         // 107520 bytes

__device__ __forceinline__ void mma16(float* d, const unsigned* a, const unsigned* b) {
    asm volatile(
        "mma.sync.aligned.m16n8k16.row.col.f32.bf16.bf16.f32 "
        "{%0,%1,%2,%3}, {%4,%5,%6,%7}, {%8,%9}, {%0,%1,%2,%3};\n"
        : "+f"(d[0]), "+f"(d[1]), "+f"(d[2]), "+f"(d[3])
        : "r"(a[0]), "r"(a[1]), "r"(a[2]), "r"(a[3]), "r"(b[0]), "r"(b[1]));
}

__device__ __forceinline__ void cpasync16(void* smem_dst, const void* gsrc, int srcsize) {
    unsigned dst = (unsigned)__cvta_generic_to_shared(smem_dst);
    asm volatile("cp.async.cg.shared.global [%0], [%1], 16, %2;\n"
                 :: "r"(dst), "l"(gsrc), "r"(srcsize));
}

__global__ __launch_bounds__(256)
void gemm_bfs(const unsigned* __restrict__ Aw,   // A' words, row pitch Kb/2
              const unsigned* __restrict__ Bw,   // B' words, [Kb/2][N]
              float* __restrict__ C, int M, int N, int Kb,
              const float* __restrict__ att_s, const float* __restrict__ att_d,
              float* __restrict__ das, float* __restrict__ dad, int hstride) {
    extern __shared__ unsigned smw[];
    const int tid  = threadIdx.x;
    const int lane = tid & 31;
    const int warp = tid >> 5;
    const int g = lane >> 2;
    const int c = lane & 3;
    const int warpM = (warp & 1) * 64;
    const int warpN = (warp >> 1) * 32;
    const int blockM = blockIdx.y * 128;
    const int blockN = blockIdx.x * 128;
    const int KbW = Kb >> 1;                 // words per A row

    float acc[4][4][4];
    #pragma unroll
    for (int mt = 0; mt < 4; mt++)
        #pragma unroll
        for (int nt = 0; nt < 4; nt++)
            #pragma unroll
            for (int i = 0; i < 4; i++) acc[mt][nt][i] = 0.f;

    const int T = Kb >> 6;                   // 64-bf16 K-tiles

    auto load_stage = [&](int t, int stg) {
        unsigned* sA = smw + stg * STG_W;
        unsigned* sB = sA + A_STG_W;
        const int k0w = t << 5;              // word offset of this tile (32 words)
        // A: 128 rows x 32 words; 16B chunk = 4 words; 8 chunks/row
        #pragma unroll
        for (int i = 0; i < 4; i++) {
            int linear = i * 256 + tid;
            int r  = linear >> 3;
            int ch = linear & 7;
            int gRow = blockM + r;
            cpasync16((char*)sA + r * (A_PITCH_W * 4) + ch * 16,
                      Aw + (size_t)gRow * KbW + k0w + ch * 4,
                      (gRow < M) ? 16 : 0);
        }
        // B: 32 pair-rows x 128 words; 32 chunks/pair-row
        #pragma unroll
        for (int i = 0; i < 4; i++) {
            int linear = i * 256 + tid;
            int pr = linear >> 5;
            int w  = linear & 31;
            cpasync16((char*)sB + pr * (B_PITCH_W * 4) + w * 16,
                      Bw + (size_t)(k0w + pr) * N + blockN + w * 4, 16);
        }
    };

    load_stage(0, 0);
    asm volatile("cp.async.commit_group;\n" ::);
    load_stage(1, 1);
    asm volatile("cp.async.commit_group;\n" ::);

    for (int t = 0; t < T; t++) {
        asm volatile("cp.async.wait_group 1;\n" ::);
        __syncthreads();

        if (t + 2 < T) load_stage(t + 2, (t + 2) % 3);
        asm volatile("cp.async.commit_group;\n" ::);

        const unsigned* sA = smw + (t % 3) * STG_W;
        const unsigned* sB = sA + A_STG_W;

        #pragma unroll
        for (int ks = 0; ks < 4; ks++) {
            const int kb2 = ks * 8;          // word offset of 16-bf16 chunk
            unsigned a[4][4], b[4][2];
            #pragma unroll
            for (int mt = 0; mt < 4; mt++) {
                int r0 = (warpM + mt * 16 + g) * A_PITCH_W + kb2 + c;
                a[mt][0] = sA[r0];
                a[mt][1] = sA[r0 + 8 * A_PITCH_W];
                a[mt][2] = sA[r0 + 4];
                a[mt][3] = sA[r0 + 8 * A_PITCH_W + 4];
            }
            #pragma unroll
            for (int nt = 0; nt < 4; nt++) {
                int coln = warpN + nt * 8 + g;
                b[nt][0] = sB[(kb2 + c)     * B_PITCH_W + coln];
                b[nt][1] = sB[(kb2 + 4 + c) * B_PITCH_W + coln];
            }
            #pragma unroll
            for (int mt = 0; mt < 4; mt++)
                #pragma unroll
                for (int nt = 0; nt < 4; nt++)
                    mma16(acc[mt][nt], a[mt], b[nt]);
        }
    }

    // ---- fused attention dot-products (N-tile == one head) ----
    if (att_s) {
        float asv[8], adv[8];
        #pragma unroll
        for (int nt = 0; nt < 4; nt++) {
            int colg = blockN + warpN + nt * 8 + 2 * c;
            asv[nt * 2]     = att_s[colg];
            asv[nt * 2 + 1] = att_s[colg + 1];
            adv[nt * 2]     = att_d[colg];
            adv[nt * 2 + 1] = att_d[colg + 1];
        }
        #pragma unroll
        for (int mt = 0; mt < 4; mt++) {
            float s0 = 0.f, d0 = 0.f, s1 = 0.f, d1 = 0.f;
            #pragma unroll
            for (int nt = 0; nt < 4; nt++) {
                s0 += acc[mt][nt][0] * asv[nt * 2] + acc[mt][nt][1] * asv[nt * 2 + 1];
                d0 += acc[mt][nt][0] * adv[nt * 2] + acc[mt][nt][1] * adv[nt * 2 + 1];
                s1 += acc[mt][nt][2] * asv[nt * 2] + acc[mt][nt][3] * asv[nt * 2 + 1];
                d1 += acc[mt][nt][2] * adv[nt * 2] + acc[mt][nt][3] * adv[nt * 2 + 1];
            }
            #pragma unroll
            for (int o = 1; o <= 2; o <<= 1) {
                s0 += __shfl_xor_sync(0xffffffffu, s0, o);
                d0 += __shfl_xor_sync(0xffffffffu, d0, o);
                s1 += __shfl_xor_sync(0xffffffffu, s1, o);
                d1 += __shfl_xor_sync(0xffffffffu, d1, o);
            }
            if (c == 0) {
                int row0 = blockM + warpM + mt * 16 + g;
                if (row0 < M) {
                    atomicAdd(&das[row0 * hstride + blockIdx.x], s0);
                    atomicAdd(&dad[row0 * hstride + blockIdx.x], d0);
                }
                int row1 = row0 + 8;
                if (row1 < M) {
                    atomicAdd(&das[row1 * hstride + blockIdx.x], s1);
                    atomicAdd(&dad[row1 * hstride + blockIdx.x], d1);
                }
            }
        }
    }

    // ---- store C ----
    #pragma unroll
    for (int mt = 0; mt < 4; mt++)
        #pragma unroll
        for (int nt = 0; nt < 4; nt++) {
            int row0 = blockM + warpM + mt * 16 + g;
            int col  = blockN + warpN + nt * 8 + 2 * c;
            if (row0 < M)
                *(float2*)(C + (size_t)row0 * N + col) =
                    make_float2(acc[mt][nt][0], acc[mt][nt][1]);
            int row1 = row0 + 8;
            if (row1 < M)
                *(float2*)(C + (size_t)row1 * N + col) =
                    make_float2(acc[mt][nt][2], acc[mt][nt][3]);
        }
}

// ---------------- GAT aggregation (CSR per-dst-node, local softmax) --------
__device__ __forceinline__ void sAtomicMaxF(float* a, float v) {
    int* ai = (int*)a;
    int old = *ai;
    while (__int_as_float(old) < v) {
        int assumed = old;
        old = atomicCAS(ai, assumed, __float_as_int(v));
        if (old == assumed) break;
    }
}

__global__ __launch_bounds__(256)
void k_agg1(const float* __restrict__ bias) {
    int n = blockIdx.x;
    int s0 = d_off[n];
    int deg = d_off[n + 1] - s0;
    __shared__ float sm[H1H], sz[H1H], sad[H1H];
    int tid = threadIdx.x;
    if (tid < H1H) { sad[tid] = d_ad1[n * H1H + tid]; sm[tid] = -1e30f; sz[tid] = 0.f; }
    __syncthreads();
    for (int idx = tid; idx < deg * H1H; idx += 256) {
        int e = idx >> 3, hh = idx & 7;
        int src = d_csr[s0 + e];
        float v = d_as1[src * H1H + hh] + sad[hh];
        v = v > 0.f ? v : NEG * v;
        sAtomicMaxF(&sm[hh], v);
    }
    __syncthreads();
    for (int idx = tid; idx < deg * H1H; idx += 256) {
        int e = idx >> 3, hh = idx & 7;
        int src = d_csr[s0 + e];
        float v = d_as1[src * H1H + hh] + sad[hh];
        v = v > 0.f ? v : NEG * v;
        atomicAdd(&sz[hh], __expf(v - sm[hh]));
    }
    __syncthreads();
    int c0 = tid * 4;
    int hh = c0 >> 7;
    float m = sm[hh], invz = 1.f / sz[hh], ad = sad[hh];
    float4 acc = make_float4(0.f, 0.f, 0.f, 0.f);
    for (int e = 0; e < deg; e++) {
        int src = d_csr[s0 + e];
        float v = d_as1[src * H1H + hh] + ad;
        v = v > 0.f ? v : NEG * v;
        float al = __expf(v - m) * invz;
        float4 hv = *(const float4*)(d_h1 + (size_t)src * F1 + c0);
        acc.x += al * hv.x; acc.y += al * hv.y;
        acc.z += al * hv.z; acc.w += al * hv.w;
    }
    float4 bb = *(const float4*)(bias + c0);
    acc.x += bb.x; acc.y += bb.y; acc.z += bb.z; acc.w += bb.w;
    *(float4*)(d_g1 + (size_t)n * F1 + c0) = acc;
}

__global__ __launch_bounds__(128)
void k_agg2(const float* __restrict__ bias) {
    int n = blockIdx.x;
    int s0 = d_off[n];
    int deg = d_off[n + 1] - s0;
    __shared__ float sm, sz, sad;
    int tid = threadIdx.x;
    if (tid == 0) { sad = d_ad2[n]; sm = -1e30f; sz = 0.f; }
    __syncthreads();
    for (int e = tid; e < deg; e += 128) {
        float v = d_as2[d_csr[s0 + e]] + sad;
        v = v > 0.f ? v : NEG * v;
        sAtomicMaxF(&sm, v);
    }
    __syncthreads();
    for (int e = tid; e < deg; e += 128) {
        float v = d_as2[d_csr[s0 + e]] + sad;
        v = v > 0.f ? v : NEG * v;
        atomicAdd(&sz, __expf(v - sm));
    }
    __syncthreads();
    float m = sm, invz = 1.f / sz, ad = sad;
    float acc = 0.f;
    for (int e = 0; e < deg; e++) {
        int src = d_csr[s0 + e];
        float v = d_as2[src] + ad;
        v = v > 0.f ? v : NEG * v;
        acc += __expf(v - m) * invz * d_h2[(size_t)src * F2 + tid];
    }
    d_g2[(size_t)n * F2 + tid] = acc + bias[tid];
}

// ---------------- BatchNorm ------------------------------------------------
__global__ void bn_stats(const float* __restrict__ x, float* __restrict__ sum,
                         float* __restrict__ sq, int F) {
    int col = blockIdx.x * 128 + threadIdx.x;
    float s = 0.f, q = 0.f;
    for (int r = blockIdx.y; r < NN; r += gridDim.y) {
        float v = x[(size_t)r * F + col];
        s += v; q += v * v;
    }
    atomicAdd(&sum[col], s);
    atomicAdd(&sq[col], q);
}

__global__ void bn_final(const float* __restrict__ sum, const float* __restrict__ sq,
                         const float* __restrict__ gamma, const float* __restrict__ beta,
                         float* __restrict__ scale, float* __restrict__ shift, int F) {
    int c = blockIdx.x * blockDim.x + threadIdx.x;
    if (c < F) {
        float mu  = sum[c] * (1.f / NN);
        float var = sq[c] * (1.f / NN) - mu * mu;
        float sc  = gamma[c] * rsqrtf(var + BNEPS);
        scale[c] = sc;
        shift[c] = beta[c] - mu * sc;
    }
}

// ---------------- classifier head (fused BN2+ELU) ---------------------------
__global__ __launch_bounds__(64)
void k_classifier(const float* __restrict__ g2, const float* __restrict__ scale,
                  const float* __restrict__ shift,
                  const float* __restrict__ Wc1, const float* __restrict__ bc1,
                  const float* __restrict__ Wc2, const float* __restrict__ bc2,
                  float* __restrict__ out) {
    int n = blockIdx.x;
    int tid = threadIdx.x;
    __shared__ float sx[128], sh[64];
    float v0 = g2[(size_t)n * F2 + tid]      * scale[tid]      + shift[tid];
    float v1 = g2[(size_t)n * F2 + 64 + tid] * scale[tid + 64] + shift[tid + 64];
    sx[tid]      = eluf(v0);
    sx[tid + 64] = eluf(v1);
    __syncthreads();
    float s = bc1[tid];
    #pragma unroll 8
    for (int k = 0; k < 128; k++) s += sx[k] * Wc1[k * 64 + tid];
    sh[tid] = fmaxf(s, 0.f);
    __syncthreads();
    if (tid < 2) {
        float o = bc2[tid];
        #pragma unroll 8
        for (int k = 0; k < 64; k++) o += sh[k] * Wc2[k * 2 + tid];
        out[n * 2 + tid] = o;
    }
}

// ---------------- launch ----------------------------------------------------
extern "C" void kernel_launch(void* const* d_in, const int* in_sizes, int n_in,
                              void* d_out, int out_size) {
    const float* x     = (const float*)d_in[0];
    const void*  ei    = d_in[1];
    const float* W1    = (const float*)d_in[2];
    const float* atts1 = (const float*)d_in[3];
    const float* attd1 = (const float*)d_in[4];
    const float* b1    = (const float*)d_in[5];
    const float* W2    = (const float*)d_in[6];
    const float* atts2 = (const float*)d_in[7];
    const float* attd2 = (const float*)d_in[8];
    const float* b2    = (const float*)d_in[9];
    const float* g1    = (const float*)d_in[10];
    const float* be1   = (const float*)d_in[11];
    const float* g2w   = (const float*)d_in[12];
    const float* be2   = (const float*)d_in[13];
    const float* Wc1   = (const float*)d_in[14];
    const float* bc1   = (const float*)d_in[15];
    const float* Wc2   = (const float*)d_in[16];
    const float* bc2   = (const float*)d_in[17];
    float*       out   = (float*)d_out;

    void *p_deg, *p_h1, *p_g2, *p_bsum, *p_bsq, *p_scale, *p_shift;
    void *p_as1, *p_ad1, *p_as2, *p_ad2, *p_h2, *p_g1;
    void *p_xs, *p_g1s, *p_w1s, *p_w2s;
    cudaGetSymbolAddress(&p_deg,   d_deg);
    cudaGetSymbolAddress(&p_h1,    d_h1);
    cudaGetSymbolAddress(&p_g1,    d_g1);
    cudaGetSymbolAddress(&p_h2,    d_h2);
    cudaGetSymbolAddress(&p_g2,    d_g2);
    cudaGetSymbolAddress(&p_bsum,  d_bsum);
    cudaGetSymbolAddress(&p_bsq,   d_bsq);
    cudaGetSymbolAddress(&p_scale, d_scale);
    cudaGetSymbolAddress(&p_shift, d_shift);
    cudaGetSymbolAddress(&p_as1,   d_as1);
    cudaGetSymbolAddress(&p_ad1,   d_ad1);
    cudaGetSymbolAddress(&p_as2,   d_as2);
    cudaGetSymbolAddress(&p_ad2,   d_ad2);
    cudaGetSymbolAddress(&p_xs,    d_xs);
    cudaGetSymbolAddress(&p_g1s,   d_g1s);
    cudaGetSymbolAddress(&p_w1s,   d_w1s);
    cudaGetSymbolAddress(&p_w2s,   d_w2s);

    cudaFuncSetAttribute(gemm_bfs, cudaFuncAttributeMaxDynamicSharedMemorySize,
                         GEMM_SMEM);

    // CSR build + conversions (independent work, fills the same stream)
    cudaMemsetAsync(p_deg, 0, NN * sizeof(int));
    k_detect<<<1, 64>>>(ei);
    k_count<<<(ETOT + 255) / 256, 256>>>(ei);
    conv_x<<<(NN * (DIN / 2) + 255) / 256, 256>>>(x);
    conv_w<<<((K1P / 2) * F1 + 255) / 256, 256>>>(W1, (unsigned*)p_w1s, DIN, F1);
    conv_w<<<((K2P / 2) * F2 + 255) / 256, 256>>>(W2, (unsigned*)p_w2s, F1, F2);
    k_scan<<<1, 1024>>>();
    k_scatter<<<(ETOT + 255) / 256, 256>>>(ei);

    // ---- GAT layer 1: split-bf16 GEMM (fused attention dots) ----
    {
        dim3 grid(F1 / 128, (NN + 127) / 128);
        gemm_bfs<<<grid, 256, GEMM_SMEM>>>((const unsigned*)p_xs,
                                           (const unsigned*)p_w1s,
                                           (float*)p_h1, NN, F1, K1P,
                                           atts1, attd1,
                                           (float*)p_as1, (float*)p_ad1, H1H);
    }
    k_agg1<<<NN, 256>>>(b1);

    // BN1 stats -> conv_g1 applies BN+ELU and writes split A' for GEMM2
    cudaMemsetAsync(p_bsum, 0, F1 * sizeof(float));
    cudaMemsetAsync(p_bsq,  0, F1 * sizeof(float));
    {
        dim3 grid(F1 / 128, 128);
        bn_stats<<<grid, 128>>>((const float*)p_g1, (float*)p_bsum, (float*)p_bsq, F1);
    }
    bn_final<<<F1 / 128, 128>>>((const float*)p_bsum, (const float*)p_bsq, g1, be1,
                                (float*)p_scale, (float*)p_shift, F1);
    conv_g1<<<(NN * (F1 / 2) + 255) / 256, 256>>>((const float*)p_scale,
                                                  (const float*)p_shift);

    // ---- GAT layer 2: split-bf16 GEMM (fused attention dots) ----
    {
        dim3 grid(F2 / 128, (NN + 127) / 128);
        gemm_bfs<<<grid, 256, GEMM_SMEM>>>((const unsigned*)p_g1s,
                                           (const unsigned*)p_w2s,
                                           (float*)p_h2, NN, F2, K2P,
                                           atts2, attd2,
                                           (float*)p_as2, (float*)p_ad2, 1);
    }
    k_agg2<<<NN, 128>>>(b2);

    // BN2 stats (apply fused into classifier)
    cudaMemsetAsync(p_bsum, 0, F2 * sizeof(float));
    cudaMemsetAsync(p_bsq,  0, F2 * sizeof(float));
    {
        dim3 grid(F2 / 128, 128);
        bn_stats<<<grid, 128>>>((const float*)p_g2, (float*)p_bsum, (float*)p_bsq, F2);
    }
    bn_final<<<1, 128>>>((const float*)p_bsum, (const float*)p_bsq, g2w, be2,
                         (float*)p_scale, (float*)p_shift, F2);

    // ---- classifier head (fused BN2+ELU) ----
    k_classifier<<<NN, 64>>>((const float*)p_g2, (const float*)p_scale,
                             (const float*)p_shift, Wc1, bc1, Wc2, bc2, out);
}

// round 10
// speedup vs baseline: 1.8701x; 1.0834x over previous
#include <cuda_runtime.h>
#include <cuda_bf16.h>

// Problem constants (fixed shapes)
#define NN   20000
#define EE   320000
#define ETOT 340000      // EE + NN self-loops
#define DIN  768
#define F1   1024        // H1*C1
#define H1H  8
#define C1C  128
#define F2   128
#define NEG  0.2f
#define BNEPS 1e-5f

#define K1P  (3 * DIN)   // 2304  triple-split K for GEMM1
#define K2P  (3 * F1)    // 3072  triple-split K for GEMM2

// ---------------- scratch (device globals; no allocation allowed) ----------
__device__ float d_h1[NN * F1];
__device__ float d_g1[NN * F1];
__device__ float d_h2[NN * F2];
__device__ float d_g2[NN * F2];
__device__ float d_as1[NN * H1H];
__device__ float d_ad1[NN * H1H];
__device__ float d_as2[NN];
__device__ float d_ad2[NN];
__device__ int   d_deg[NN];
__device__ int   d_off[NN + 1];
__device__ int   d_cnt[NN];
__device__ int   d_csr[ETOT];
__device__ float d_bsum[F1];
__device__ float d_bsq[F1];
__device__ float d_scale[F1];
__device__ float d_shift[F1];
__device__ int   d_is64;
// split-bf16 operands (words = bf16x2, k-pair packed: low=even k, high=odd k)
__device__ unsigned d_xs [NN * (K1P / 2)];        // A' for GEMM1, row-major
__device__ unsigned d_g1s[NN * (K2P / 2)];        // A' for GEMM2, row-major
__device__ unsigned d_w1s[(K1P / 2) * F1];        // B' pair-interleaved [k/2][n]
__device__ unsigned d_w2s[(K2P / 2) * F2];

// ---------------- bf16 helpers ----------------------------------------------
__device__ __forceinline__ unsigned packbf(float fhi, float flo) {
    unsigned r;
    asm("cvt.rn.bf16x2.f32 %0, %1, %2;\n" : "=r"(r) : "f"(fhi), "f"(flo));
    return r;
}
__device__ __forceinline__ float bfhi(float v) {
    unsigned r = packbf(v, v);
    return __uint_as_float(r & 0xffff0000u);
}
__device__ __forceinline__ float eluf(float v) {
    return v > 0.f ? v : (__expf(v) - 1.f);
}

// ---------------- dtype detection (parallel) --------------------------------
__global__ void k_detect(const void* ei) {
    __shared__ int ok;
    int t = threadIdx.x;
    if (t == 0) ok = 1;
    __syncthreads();
    long long v = ((const long long*)ei)[t];
    if (v < 0 || v >= NN) ok = 0;
    __syncthreads();
    if (t == 0) d_is64 = ok;
}

__device__ __forceinline__ int load_idx(const void* ei, int i) {
    int v = d_is64 ? (int)((const long long*)ei)[i] : ((const int*)ei)[i];
    v = v < 0 ? 0 : (v >= NN ? NN - 1 : v);
    return v;
}

// ---------------- CSR build ------------------------------------------------
__global__ void k_count(const void* __restrict__ ei) {
    int i = blockIdx.x * blockDim.x + threadIdx.x;
    if (i >= ETOT) return;
    if (i < NN) d_cnt[i] = 0;                 // zero cnt here (used by scatter)
    int dst = (i < EE) ? load_idx(ei, EE + i) : (i - EE);
    atomicAdd(&d_deg[dst], 1);
}

__global__ void k_scan() {
    __shared__ int s[1024];
    __shared__ int carry;
    int tid = threadIdx.x;
    if (tid == 0) { carry = 0; d_off[0] = 0; }
    __syncthreads();
    for (int base = 0; base < NN; base += 1024) {
        int i = base + tid;
        int v = (i < NN) ? d_deg[i] : 0;
        s[tid] = v;
        __syncthreads();
        #pragma unroll
        for (int ofs = 1; ofs < 1024; ofs <<= 1) {
            int t = (tid >= ofs) ? s[tid - ofs] : 0;
            __syncthreads();
            s[tid] += t;
            __syncthreads();
        }
        if (i < NN) d_off[i + 1] = carry + s[tid];
        __syncthreads();
        if (tid == 0) carry += s[1023];
        __syncthreads();
    }
}

__global__ void k_scatter(const void* __restrict__ ei) {
    int i = blockIdx.x * blockDim.x + threadIdx.x;
    if (i >= ETOT) return;
    if (i < F1) { d_bsum[i] = 0.f; d_bsq[i] = 0.f; }   // zero BN1 accumulators
    int src, dst;
    if (i < EE) { src = load_idx(ei, i); dst = load_idx(ei, EE + i); }
    else        { src = dst = i - EE; }
    int p = d_off[dst] + atomicAdd(&d_cnt[dst], 1);
    d_csr[p] = src;
}

// ---------------- conversion passes -----------------------------------------
// A' row layout (words per row = 3K/2): [hi(K/2) | lo(K/2) | hi(K/2)]
__global__ void conv_x(const float* __restrict__ X) {
    int idx = blockIdx.x * blockDim.x + threadIdx.x;
    if (idx >= NN * (DIN / 2)) return;
    int r = idx / (DIN / 2), kp = idx % (DIN / 2);
    float2 v = *(const float2*)(X + (size_t)r * DIN + 2 * kp);
    float h0 = bfhi(v.x), h1 = bfhi(v.y);
    unsigned hp = packbf(h1, h0);
    unsigned lp = packbf(v.y - h1, v.x - h0);
    unsigned* row = d_xs + (size_t)r * (K1P / 2);
    row[kp] = hp;
    row[DIN / 2 + kp] = lp;
    row[DIN + kp] = hp;
}

// g1 -> BN1+ELU -> split triple (fused apply); also zeroes BN2 accumulators
__global__ void conv_g1(const float* __restrict__ scale,
                        const float* __restrict__ shift) {
    int idx = blockIdx.x * blockDim.x + threadIdx.x;
    if (idx < F2) { d_bsum[idx] = 0.f; d_bsq[idx] = 0.f; }
    if (idx >= NN * (F1 / 2)) return;
    int r = idx / (F1 / 2), kp = idx % (F1 / 2);
    float2 v = *(const float2*)(d_g1 + (size_t)r * F1 + 2 * kp);
    float2 sc = *(const float2*)(scale + 2 * kp);
    float2 sh = *(const float2*)(shift + 2 * kp);
    float a0 = eluf(v.x * sc.x + sh.x);
    float a1 = eluf(v.y * sc.y + sh.y);
    float h0 = bfhi(a0), h1 = bfhi(a1);
    unsigned hp = packbf(h1, h0);
    unsigned lp = packbf(a1 - h1, a0 - h0);
    unsigned* row = d_g1s + (size_t)r * (K2P / 2);
    row[kp] = hp;
    row[F1 / 2 + kp] = lp;
    row[F1 + kp] = hp;
}

// W [K][N] fp32 -> W' pair-interleaved [3K/2][N] words: segs [hi | hi | lo]
__global__ void conv_w(const float* __restrict__ W, unsigned* __restrict__ Wp,
                       int K, int N) {
    int idx = blockIdx.x * blockDim.x + threadIdx.x;
    int tot = (3 * K / 2) * N;
    if (idx >= tot) return;
    int p = idx / N, n = idx % N;
    int k2 = 2 * p;
    int k; bool lo;
    if (k2 < K)          { k = k2;         lo = false; }
    else if (k2 < 2 * K) { k = k2 - K;     lo = false; }
    else                 { k = k2 - 2 * K; lo = true;  }
    float v0 = W[(size_t)k * N + n];
    float v1 = W[(size_t)(k + 1) * N + n];
    unsigned r;
    if (!lo) r = packbf(bfhi(v1), bfhi(v0));
    else     r = packbf(v1 - bfhi(v1), v0 - bfhi(v0));
    Wp[(size_t)p * N + n] = r;
}

// ---------------- split-bf16 tensor-core GEMM -------------------------------
#define A_PITCH_W 36
#define B_PITCH_W 136
#define A_STG_W   (128 * A_PITCH_W)
#define B_STG_W   (32 * B_PITCH_W)
#define STG_W     (A_STG_W + B_STG_W)
#define GEMM_SMEM (3 * STG_W * 4)             // 107520 bytes

__device__ __forceinline__ void mma16(float* d, const unsigned* a, const unsigned* b) {
    asm volatile(
        "mma.sync.aligned.m16n8k16.row.col.f32.bf16.bf16.f32 "
        "{%0,%1,%2,%3}, {%4,%5,%6,%7}, {%8,%9}, {%0,%1,%2,%3};\n"
        : "+f"(d[0]), "+f"(d[1]), "+f"(d[2]), "+f"(d[3])
        : "r"(a[0]), "r"(a[1]), "r"(a[2]), "r"(a[3]), "r"(b[0]), "r"(b[1]));
}

__device__ __forceinline__ void cpasync16(void* smem_dst, const void* gsrc, int srcsize) {
    unsigned dst = (unsigned)__cvta_generic_to_shared(smem_dst);
    asm volatile("cp.async.cg.shared.global [%0], [%1], 16, %2;\n"
                 :: "r"(dst), "l"(gsrc), "r"(srcsize));
}

__global__ __launch_bounds__(256)
void gemm_bfs(const unsigned* __restrict__ Aw,
              const unsigned* __restrict__ Bw,
              float* __restrict__ C, int M, int N, int Kb,
              const float* __restrict__ att_s, const float* __restrict__ att_d,
              float* __restrict__ das, float* __restrict__ dad, int hstride) {
    extern __shared__ unsigned smw[];
    const int tid  = threadIdx.x;
    const int lane = tid & 31;
    const int warp = tid >> 5;
    const int g = lane >> 2;
    const int c = lane & 3;
    const int warpM = (warp & 1) * 64;
    const int warpN = (warp >> 1) * 32;
    const int blockM = blockIdx.y * 128;
    const int blockN = blockIdx.x * 128;
    const int KbW = Kb >> 1;

    float acc[4][4][4];
    #pragma unroll
    for (int mt = 0; mt < 4; mt++)
        #pragma unroll
        for (int nt = 0; nt < 4; nt++)
            #pragma unroll
            for (int i = 0; i < 4; i++) acc[mt][nt][i] = 0.f;

    const int T = Kb >> 6;

    auto load_stage = [&](int t, int stg) {
        unsigned* sA = smw + stg * STG_W;
        unsigned* sB = sA + A_STG_W;
        const int k0w = t << 5;
        #pragma unroll
        for (int i = 0; i < 4; i++) {
            int linear = i * 256 + tid;
            int r  = linear >> 3;
            int ch = linear & 7;
            int gRow = blockM + r;
            cpasync16((char*)sA + r * (A_PITCH_W * 4) + ch * 16,
                      Aw + (size_t)gRow * KbW + k0w + ch * 4,
                      (gRow < M) ? 16 : 0);
        }
        #pragma unroll
        for (int i = 0; i < 4; i++) {
            int linear = i * 256 + tid;
            int pr = linear >> 5;
            int w  = linear & 31;
            cpasync16((char*)sB + pr * (B_PITCH_W * 4) + w * 16,
                      Bw + (size_t)(k0w + pr) * N + blockN + w * 4, 16);
        }
    };

    load_stage(0, 0);
    asm volatile("cp.async.commit_group;\n" ::);
    load_stage(1, 1);
    asm volatile("cp.async.commit_group;\n" ::);

    for (int t = 0; t < T; t++) {
        asm volatile("cp.async.wait_group 1;\n" ::);
        __syncthreads();

        if (t + 2 < T) load_stage(t + 2, (t + 2) % 3);
        asm volatile("cp.async.commit_group;\n" ::);

        const unsigned* sA = smw + (t % 3) * STG_W;
        const unsigned* sB = sA + A_STG_W;

        #pragma unroll
        for (int ks = 0; ks < 4; ks++) {
            const int kb2 = ks * 8;
            unsigned a[4][4], b[4][2];
            #pragma unroll
            for (int mt = 0; mt < 4; mt++) {
                int r0 = (warpM + mt * 16 + g) * A_PITCH_W + kb2 + c;
                a[mt][0] = sA[r0];
                a[mt][1] = sA[r0 + 8 * A_PITCH_W];
                a[mt][2] = sA[r0 + 4];
                a[mt][3] = sA[r0 + 8 * A_PITCH_W + 4];
            }
            #pragma unroll
            for (int nt = 0; nt < 4; nt++) {
                int coln = warpN + nt * 8 + g;
                b[nt][0] = sB[(kb2 + c)     * B_PITCH_W + coln];
                b[nt][1] = sB[(kb2 + 4 + c) * B_PITCH_W + coln];
            }
            #pragma unroll
            for (int mt = 0; mt < 4; mt++)
                #pragma unroll
                for (int nt = 0; nt < 4; nt++)
                    mma16(acc[mt][nt], a[mt], b[nt]);
        }
    }

    // ---- fused attention dots: smem cross-warp reduction, plain store ----
    // Each (row, head) is produced by exactly this block (N-tile == head),
    // so no global atomics and no pre-zeroed das/dad needed.
    if (att_s) {
        __syncthreads();                       // mainloop done; reuse smem
        float* sred = (float*)smw;             // [128 rows][2]
        sred[tid] = 0.f;                       // 256 threads cover 256 floats
        __syncthreads();
        float asv[8], adv[8];
        #pragma unroll
        for (int nt = 0; nt < 4; nt++) {
            int colg = blockN + warpN + nt * 8 + 2 * c;
            asv[nt * 2]     = att_s[colg];
            asv[nt * 2 + 1] = att_s[colg + 1];
            adv[nt * 2]     = att_d[colg];
            adv[nt * 2 + 1] = att_d[colg + 1];
        }
        #pragma unroll
        for (int mt = 0; mt < 4; mt++) {
            float s0 = 0.f, d0 = 0.f, s1 = 0.f, d1 = 0.f;
            #pragma unroll
            for (int nt = 0; nt < 4; nt++) {
                s0 += acc[mt][nt][0] * asv[nt * 2] + acc[mt][nt][1] * asv[nt * 2 + 1];
                d0 += acc[mt][nt][0] * adv[nt * 2] + acc[mt][nt][1] * adv[nt * 2 + 1];
                s1 += acc[mt][nt][2] * asv[nt * 2] + acc[mt][nt][3] * asv[nt * 2 + 1];
                d1 += acc[mt][nt][2] * adv[nt * 2] + acc[mt][nt][3] * adv[nt * 2 + 1];
            }
            #pragma unroll
            for (int o = 1; o <= 2; o <<= 1) {
                s0 += __shfl_xor_sync(0xffffffffu, s0, o);
                d0 += __shfl_xor_sync(0xffffffffu, d0, o);
                s1 += __shfl_xor_sync(0xffffffffu, s1, o);
                d1 += __shfl_xor_sync(0xffffffffu, d1, o);
            }
            if (c == 0) {
                int r0 = warpM + mt * 16 + g;
                atomicAdd(&sred[r0 * 2],           s0);
                atomicAdd(&sred[r0 * 2 + 1],       d0);
                atomicAdd(&sred[(r0 + 8) * 2],     s1);
                atomicAdd(&sred[(r0 + 8) * 2 + 1], d1);
            }
        }
        __syncthreads();
        if (tid < 128) {
            int row = blockM + tid;
            if (row < M) {
                das[row * hstride + blockIdx.x] = sred[tid * 2];
                dad[row * hstride + blockIdx.x] = sred[tid * 2 + 1];
            }
        }
    }

    // ---- store C ----
    #pragma unroll
    for (int mt = 0; mt < 4; mt++)
        #pragma unroll
        for (int nt = 0; nt < 4; nt++) {
            int row0 = blockM + warpM + mt * 16 + g;
            int col  = blockN + warpN + nt * 8 + 2 * c;
            if (row0 < M)
                *(float2*)(C + (size_t)row0 * N + col) =
                    make_float2(acc[mt][nt][0], acc[mt][nt][1]);
            int row1 = row0 + 8;
            if (row1 < M)
                *(float2*)(C + (size_t)row1 * N + col) =
                    make_float2(acc[mt][nt][2], acc[mt][nt][3]);
        }
}

// ---------------- GAT aggregation (CSR per-dst-node, local softmax) --------
__device__ __forceinline__ void sAtomicMaxF(float* a, float v) {
    int* ai = (int*)a;
    int old = *ai;
    while (__int_as_float(old) < v) {
        int assumed = old;
        old = atomicCAS(ai, assumed, __float_as_int(v));
        if (old == assumed) break;
    }
}

__global__ __launch_bounds__(256)
void k_agg1(const float* __restrict__ bias) {
    int n = blockIdx.x;
    int s0 = d_off[n];
    int deg = d_off[n + 1] - s0;
    __shared__ float sm[H1H], sz[H1H], sad[H1H];
    int tid = threadIdx.x;
    if (tid < H1H) { sad[tid] = d_ad1[n * H1H + tid]; sm[tid] = -1e30f; sz[tid] = 0.f; }
    __syncthreads();
    for (int idx = tid; idx < deg * H1H; idx += 256) {
        int e = idx >> 3, hh = idx & 7;
        int src = d_csr[s0 + e];
        float v = d_as1[src * H1H + hh] + sad[hh];
        v = v > 0.f ? v : NEG * v;
        sAtomicMaxF(&sm[hh], v);
    }
    __syncthreads();
    for (int idx = tid; idx < deg * H1H; idx += 256) {
        int e = idx >> 3, hh = idx & 7;
        int src = d_csr[s0 + e];
        float v = d_as1[src * H1H + hh] + sad[hh];
        v = v > 0.f ? v : NEG * v;
        atomicAdd(&sz[hh], __expf(v - sm[hh]));
    }
    __syncthreads();
    int c0 = tid * 4;
    int hh = c0 >> 7;
    float m = sm[hh], invz = 1.f / sz[hh], ad = sad[hh];
    float4 acc = make_float4(0.f, 0.f, 0.f, 0.f);
    for (int e = 0; e < deg; e++) {
        int src = d_csr[s0 + e];
        float v = d_as1[src * H1H + hh] + ad;
        v = v > 0.f ? v : NEG * v;
        float al = __expf(v - m) * invz;
        float4 hv = *(const float4*)(d_h1 + (size_t)src * F1 + c0);
        acc.x += al * hv.x; acc.y += al * hv.y;
        acc.z += al * hv.z; acc.w += al * hv.w;
    }
    float4 bb = *(const float4*)(bias + c0);
    acc.x += bb.x; acc.y += bb.y; acc.z += bb.z; acc.w += bb.w;
    *(float4*)(d_g1 + (size_t)n * F1 + c0) = acc;
}

__global__ __launch_bounds__(128)
void k_agg2(const float* __restrict__ bias) {
    int n = blockIdx.x;
    int s0 = d_off[n];
    int deg = d_off[n + 1] - s0;
    __shared__ float sm, sz, sad;
    int tid = threadIdx.x;
    if (tid == 0) { sad = d_ad2[n]; sm = -1e30f; sz = 0.f; }
    __syncthreads();
    for (int e = tid; e < deg; e += 128) {
        float v = d_as2[d_csr[s0 + e]] + sad;
        v = v > 0.f ? v : NEG * v;
        sAtomicMaxF(&sm, v);
    }
    __syncthreads();
    for (int e = tid; e < deg; e += 128) {
        float v = d_as2[d_csr[s0 + e]] + sad;
        v = v > 0.f ? v : NEG * v;
        atomicAdd(&sz, __expf(v - sm));
    }
    __syncthreads();
    float m = sm, invz = 1.f / sz, ad = sad;
    float acc = 0.f;
    for (int e = 0; e < deg; e++) {
        int src = d_csr[s0 + e];
        float v = d_as2[src] + ad;
        v = v > 0.f ? v : NEG * v;
        acc += __expf(v - m) * invz * d_h2[(size_t)src * F2 + tid];
    }
    d_g2[(size_t)n * F2 + tid] = acc + bias[tid];
}

// ---------------- BatchNorm ------------------------------------------------
__global__ void bn_stats(const float* __restrict__ x, float* __restrict__ sum,
                         float* __restrict__ sq, int F) {
    int col = blockIdx.x * 128 + threadIdx.x;
    float s = 0.f, q = 0.f;
    for (int r = blockIdx.y; r < NN; r += gridDim.y) {
        float v = x[(size_t)r * F + col];
        s += v; q += v * v;
    }
    atomicAdd(&sum[col], s);
    atomicAdd(&sq[col], q);
}

__global__ void bn_final(const float* __restrict__ sum, const float* __restrict__ sq,
                         const float* __restrict__ gamma, const float* __restrict__ beta,
                         float* __restrict__ scale, float* __restrict__ shift, int F) {
    int c = blockIdx.x * blockDim.x + threadIdx.x;
    if (c < F) {
        float mu  = sum[c] * (1.f / NN);
        float var = sq[c] * (1.f / NN) - mu * mu;
        float sc  = gamma[c] * rsqrtf(var + BNEPS);
        scale[c] = sc;
        shift[c] = beta[c] - mu * sc;
    }
}

// ---------------- classifier head (fused BN2+ELU) ---------------------------
__global__ __launch_bounds__(64)
void k_classifier(const float* __restrict__ g2, const float* __restrict__ scale,
                  const float* __restrict__ shift,
                  const float* __restrict__ Wc1, const float* __restrict__ bc1,
                  const float* __restrict__ Wc2, const float* __restrict__ bc2,
                  float* __restrict__ out) {
    int n = blockIdx.x;
    int tid = threadIdx.x;
    __shared__ float sx[128], sh[64];
    float v0 = g2[(size_t)n * F2 + tid]      * scale[tid]      + shift[tid];
    float v1 = g2[(size_t)n * F2 + 64 + tid] * scale[tid + 64] + shift[tid + 64];
    sx[tid]      = eluf(v0);
    sx[tid + 64] = eluf(v1);
    __syncthreads();
    float s = bc1[tid];
    #pragma unroll 8
    for (int k = 0; k < 128; k++) s += sx[k] * Wc1[k * 64 + tid];
    sh[tid] = fmaxf(s, 0.f);
    __syncthreads();
    if (tid < 2) {
        float o = bc2[tid];
        #pragma unroll 8
        for (int k = 0; k < 64; k++) o += sh[k] * Wc2[k * 2 + tid];
        out[n * 2 + tid] = o;
    }
}

// ---------------- launch ----------------------------------------------------
extern "C" void kernel_launch(void* const* d_in, const int* in_sizes, int n_in,
                              void* d_out, int out_size) {
    const float* x     = (const float*)d_in[0];
    const void*  ei    = d_in[1];
    const float* W1    = (const float*)d_in[2];
    const float* atts1 = (const float*)d_in[3];
    const float* attd1 = (const float*)d_in[4];
    const float* b1    = (const float*)d_in[5];
    const float* W2    = (const float*)d_in[6];
    const float* atts2 = (const float*)d_in[7];
    const float* attd2 = (const float*)d_in[8];
    const float* b2    = (const float*)d_in[9];
    const float* g1    = (const float*)d_in[10];
    const float* be1   = (const float*)d_in[11];
    const float* g2w   = (const float*)d_in[12];
    const float* be2   = (const float*)d_in[13];
    const float* Wc1   = (const float*)d_in[14];
    const float* bc1   = (const float*)d_in[15];
    const float* Wc2   = (const float*)d_in[16];
    const float* bc2   = (const float*)d_in[17];
    float*       out   = (float*)d_out;

    void *p_deg, *p_h1, *p_g2, *p_bsum, *p_bsq, *p_scale, *p_shift;
    void *p_as1, *p_ad1, *p_as2, *p_ad2, *p_h2, *p_g1;
    void *p_xs, *p_g1s, *p_w1s, *p_w2s;
    cudaGetSymbolAddress(&p_deg,   d_deg);
    cudaGetSymbolAddress(&p_h1,    d_h1);
    cudaGetSymbolAddress(&p_g1,    d_g1);
    cudaGetSymbolAddress(&p_h2,    d_h2);
    cudaGetSymbolAddress(&p_g2,    d_g2);
    cudaGetSymbolAddress(&p_bsum,  d_bsum);
    cudaGetSymbolAddress(&p_bsq,   d_bsq);
    cudaGetSymbolAddress(&p_scale, d_scale);
    cudaGetSymbolAddress(&p_shift, d_shift);
    cudaGetSymbolAddress(&p_as1,   d_as1);
    cudaGetSymbolAddress(&p_ad1,   d_ad1);
    cudaGetSymbolAddress(&p_as2,   d_as2);
    cudaGetSymbolAddress(&p_ad2,   d_ad2);
    cudaGetSymbolAddress(&p_xs,    d_xs);
    cudaGetSymbolAddress(&p_g1s,   d_g1s);
    cudaGetSymbolAddress(&p_w1s,   d_w1s);
    cudaGetSymbolAddress(&p_w2s,   d_w2s);

    cudaFuncSetAttribute(gemm_bfs, cudaFuncAttributeMaxDynamicSharedMemorySize,
                         GEMM_SMEM);

    // Launch order puts GEMM1 at slot 5 (incl. memset) for ncu -s 5 capture.
    conv_x<<<(NN * (DIN / 2) + 255) / 256, 256>>>(x);                      // 1
    conv_w<<<((K1P / 2) * F1 + 255) / 256, 256>>>(W1, (unsigned*)p_w1s, DIN, F1); // 2
    conv_w<<<((K2P / 2) * F2 + 255) / 256, 256>>>(W2, (unsigned*)p_w2s, F1, F2);  // 3
    cudaMemsetAsync(p_deg, 0, NN * sizeof(int));                            // 4

    // ---- GAT layer 1: split-bf16 GEMM (fused attention dots) ----
    {
        dim3 grid(F1 / 128, (NN + 127) / 128);
        gemm_bfs<<<grid, 256, GEMM_SMEM>>>((const unsigned*)p_xs,          // 5
                                           (const unsigned*)p_w1s,
                                           (float*)p_h1, NN, F1, K1P,
                                           atts1, attd1,
                                           (float*)p_as1, (float*)p_ad1, H1H);
    }

    // CSR build (needed only by agg kernels)
    k_detect<<<1, 64>>>(ei);
    k_count<<<(ETOT + 255) / 256, 256>>>(ei);
    k_scan<<<1, 1024>>>();
    k_scatter<<<(ETOT + 255) / 256, 256>>>(ei);   // also zeroes BN1 accumulators

    k_agg1<<<NN, 256>>>(b1);

    // BN1 stats -> conv_g1 applies BN+ELU, writes split A', zeroes BN2 accs
    {
        dim3 grid(F1 / 128, 128);
        bn_stats<<<grid, 128>>>((const float*)p_g1, (float*)p_bsum, (float*)p_bsq, F1);
    }
    bn_final<<<F1 / 128, 128>>>((const float*)p_bsum, (const float*)p_bsq, g1, be1,
                                (float*)p_scale, (float*)p_shift, F1);
    conv_g1<<<(NN * (F1 / 2) + 255) / 256, 256>>>((const float*)p_scale,
                                                  (const float*)p_shift);

    // ---- GAT layer 2: split-bf16 GEMM (fused attention dots) ----
    {
        dim3 grid(F2 / 128, (NN + 127) / 128);
        gemm_bfs<<<grid, 256, GEMM_SMEM>>>((const unsigned*)p_g1s,
                                           (const unsigned*)p_w2s,
                                           (float*)p_h2, NN, F2, K2P,
                                           atts2, attd2,
                                           (float*)p_as2, (float*)p_ad2, 1);
    }
    k_agg2<<<NN, 128>>>(b2);

    // BN2 stats (apply fused into classifier)
    {
        dim3 grid(F2 / 128, 128);
        bn_stats<<<grid, 128>>>((const float*)p_g2, (float*)p_bsum, (float*)p_bsq, F2);
    }
    bn_final<<<1, 128>>>((const float*)p_bsum, (const float*)p_bsq, g2w, be2,
                         (float*)p_scale, (float*)p_shift, F2);

    // ---- classifier head (fused BN2+ELU) ----
    k_classifier<<<NN, 64>>>((const float*)p_g2, (const float*)p_scale,
                             (const float*)p_shift, Wc1, bc1, Wc2, bc2, out);
}

// round 13
// speedup vs baseline: 1.9421x; 1.0385x over previous
#include <cuda_runtime.h>
#include <cuda_bf16.h>
#include <cstdint>

// Problem constants (fixed shapes)
#define NN   20000
#define EE   320000
#define ETOT 340000      // EE + NN self-loops
#define DIN  768
#define F1   1024        // H1*C1
#define H1H  8
#define C1C  128
#define F2   128
#define NEG  0.2f
#define BNEPS 1e-5f

#define K1P  (3 * DIN)   // 2304  triple-split K for GEMM1
#define K2P  (3 * F1)    // 3072  triple-split K for GEMM2

// ---------------- scratch (device globals; no allocation allowed) ----------
__device__ float d_h1[NN * F1];
__device__ float d_g1[NN * F1];
__device__ float d_h2[NN * F2];
__device__ float d_g2[NN * F2];
__device__ float d_as1[NN * H1H];
__device__ float d_ad1[NN * H1H];
__device__ float d_as2[NN];
__device__ float d_ad2[NN];
__device__ int   d_deg[NN];
__device__ int   d_off[NN + 1];
__device__ int   d_cnt[NN];
__device__ int   d_csr[ETOT];
__device__ float d_bsum[F1];
__device__ float d_bsq[F1];
__device__ float d_scale[F1];
__device__ float d_shift[F1];
__device__ int   d_is64;
// split-bf16 operands (words = bf16x2; low half = even k, high = odd k)
__device__ unsigned d_xs [NN * (K1P / 2)];        // A' GEMM1 [row][3K/2 words]
__device__ unsigned d_g1s[NN * (K2P / 2)];        // A' GEMM2
__device__ unsigned d_w1t[F1 * (K1P / 2)];        // B'' GEMM1 [n][3K/2 words]
__device__ unsigned d_w2t[F2 * (K2P / 2)];        // B'' GEMM2

// ---------------- bf16 helpers ----------------------------------------------
__device__ __forceinline__ unsigned packbf(float fhi, float flo) {
    unsigned r;
    asm("cvt.rn.bf16x2.f32 %0, %1, %2;\n" : "=r"(r) : "f"(fhi), "f"(flo));
    return r;
}
__device__ __forceinline__ float bfhi(float v) {
    unsigned r = packbf(v, v);
    return __uint_as_float(r & 0xffff0000u);
}
__device__ __forceinline__ float eluf(float v) {
    return v > 0.f ? v : (__expf(v) - 1.f);
}
__device__ __forceinline__ uint32_t smem_u32(const void* p) {
    uint32_t a;
    asm("{ .reg .u64 t; cvta.to.shared.u64 t, %1; cvt.u32.u64 %0, t; }"
        : "=r"(a) : "l"(p));
    return a;
}
__device__ __forceinline__ void cpasync16(uint32_t smem_dst, const void* gsrc, int srcsize) {
    asm volatile("cp.async.cg.shared.global [%0], [%1], 16, %2;\n"
                 :: "r"(smem_dst), "l"(gsrc), "r"(srcsize));
}
__device__ __forceinline__ uint32_t swz(uint32_t off) {   // SW128 swizzle
    return off ^ ((off >> 3) & 0x70);
}
__device__ __forceinline__ void mma16(float* d, const unsigned* a, const unsigned* b) {
    asm volatile(
        "mma.sync.aligned.m16n8k16.row.col.f32.bf16.bf16.f32 "
        "{%0,%1,%2,%3}, {%4,%5,%6,%7}, {%8,%9}, {%0,%1,%2,%3};\n"
        : "+f"(d[0]), "+f"(d[1]), "+f"(d[2]), "+f"(d[3])
        : "r"(a[0]), "r"(a[1]), "r"(a[2]), "r"(a[3]), "r"(b[0]), "r"(b[1]));
}
__device__ __forceinline__ void ldm4(unsigned* r, uint32_t addr) {
    asm volatile("ldmatrix.sync.aligned.m8n8.x4.shared.b16 {%0,%1,%2,%3}, [%4];"
                 : "=r"(r[0]), "=r"(r[1]), "=r"(r[2]), "=r"(r[3]) : "r"(addr));
}

// ---------------- dtype detection (parallel) --------------------------------
__global__ void k_detect(const void* ei) {
    __shared__ int ok;
    int t = threadIdx.x;
    if (t == 0) ok = 1;
    __syncthreads();
    long long v = ((const long long*)ei)[t];
    if (v < 0 || v >= NN) ok = 0;
    __syncthreads();
    if (t == 0) d_is64 = ok;
}

__device__ __forceinline__ int load_idx(const void* ei, int i) {
    int v = d_is64 ? (int)((const long long*)ei)[i] : ((const int*)ei)[i];
    v = v < 0 ? 0 : (v >= NN ? NN - 1 : v);
    return v;
}

// ---------------- CSR build ------------------------------------------------
__global__ void k_count(const void* __restrict__ ei) {
    int i = blockIdx.x * blockDim.x + threadIdx.x;
    if (i >= ETOT) return;
    if (i < NN) d_cnt[i] = 0;
    int dst = (i < EE) ? load_idx(ei, EE + i) : (i - EE);
    atomicAdd(&d_deg[dst], 1);
}

__global__ void k_scan() {
    __shared__ int s[1024];
    __shared__ int carry;
    int tid = threadIdx.x;
    if (tid == 0) { carry = 0; d_off[0] = 0; }
    __syncthreads();
    for (int base = 0; base < NN; base += 1024) {
        int i = base + tid;
        int v = (i < NN) ? d_deg[i] : 0;
        s[tid] = v;
        __syncthreads();
        #pragma unroll
        for (int ofs = 1; ofs < 1024; ofs <<= 1) {
            int t = (tid >= ofs) ? s[tid - ofs] : 0;
            __syncthreads();
            s[tid] += t;
            __syncthreads();
        }
        if (i < NN) d_off[i + 1] = carry + s[tid];
        __syncthreads();
        if (tid == 0) carry += s[1023];
        __syncthreads();
    }
}

__global__ void k_scatter(const void* __restrict__ ei) {
    int i = blockIdx.x * blockDim.x + threadIdx.x;
    if (i >= ETOT) return;
    if (i < F1) { d_bsum[i] = 0.f; d_bsq[i] = 0.f; }
    int src, dst;
    if (i < EE) { src = load_idx(ei, i); dst = load_idx(ei, EE + i); }
    else        { src = dst = i - EE; }
    int p = d_off[dst] + atomicAdd(&d_cnt[dst], 1);
    d_csr[p] = src;
}

// ---------------- conversion passes -----------------------------------------
// A' row layout (words per row = 3K/2): [hi(K/2) | lo(K/2) | hi(K/2)]
__global__ void conv_x(const float* __restrict__ X) {
    int idx = blockIdx.x * blockDim.x + threadIdx.x;
    if (idx >= NN * (DIN / 2)) return;
    int r = idx / (DIN / 2), kp = idx % (DIN / 2);
    float2 v = *(const float2*)(X + (size_t)r * DIN + 2 * kp);
    float h0 = bfhi(v.x), h1 = bfhi(v.y);
    unsigned hp = packbf(h1, h0);
    unsigned lp = packbf(v.y - h1, v.x - h0);
    unsigned* row = d_xs + (size_t)r * (K1P / 2);
    row[kp] = hp;
    row[DIN / 2 + kp] = lp;
    row[DIN + kp] = hp;
}

// g1 -> BN1+ELU -> split triple; also zeroes BN2 accumulators
__global__ void conv_g1(const float* __restrict__ scale,
                        const float* __restrict__ shift) {
    int idx = blockIdx.x * blockDim.x + threadIdx.x;
    if (idx < F2) { d_bsum[idx] = 0.f; d_bsq[idx] = 0.f; }
    if (idx >= NN * (F1 / 2)) return;
    int r = idx / (F1 / 2), kp = idx % (F1 / 2);
    float2 v = *(const float2*)(d_g1 + (size_t)r * F1 + 2 * kp);
    float2 sc = *(const float2*)(scale + 2 * kp);
    float2 sh = *(const float2*)(shift + 2 * kp);
    float a0 = eluf(v.x * sc.x + sh.x);
    float a1 = eluf(v.y * sc.y + sh.y);
    float h0 = bfhi(a0), h1 = bfhi(a1);
    unsigned hp = packbf(h1, h0);
    unsigned lp = packbf(a1 - h1, a0 - h0);
    unsigned* row = d_g1s + (size_t)r * (K2P / 2);
    row[kp] = hp;
    row[F1 / 2 + kp] = lp;
    row[F1 + kp] = hp;
}

// W [K][N] fp32 -> W'' transposed split [N][3K/2] words, segs [hi | hi | lo]
__global__ void conv_wt(const float* __restrict__ W, unsigned* __restrict__ Wt,
                        int K, int N) {
    int idx = blockIdx.x * blockDim.x + threadIdx.x;
    int rowW = 3 * K / 2;
    if (idx >= N * rowW) return;
    int n = idx / rowW, p = idx % rowW;
    int k2 = 2 * p;
    int k; bool lo;
    if (k2 < K)          { k = k2;         lo = false; }
    else if (k2 < 2 * K) { k = k2 - K;     lo = false; }
    else                 { k = k2 - 2 * K; lo = true;  }
    float v0 = W[(size_t)k * N + n];
    float v1 = W[(size_t)(k + 1) * N + n];
    unsigned r;
    if (!lo) r = packbf(bfhi(v1), bfhi(v0));
    else     r = packbf(v1 - bfhi(v1), v0 - bfhi(v0));
    Wt[(size_t)n * rowW + p] = r;
}

// ---------------- split-bf16 HMMA GEMM with ldmatrix -------------------------
// C[M,N] = A'[M,Kb] @ B''[N,Kb]^T (bf16, fp32 accum). Block tile 128x128,
// K-tile 64 bf16, 3-stage cp.async. Tiles stored as 128 rows x 128B with SW128
// swizzle; fragments fetched via ldmatrix.m8n8.x4. Fused attention epilogue.
#define STG_BYTES 32768                      // A 16KB + B 16KB per stage
#define GEMM_SMEM (3 * STG_BYTES)            // 98304 bytes

__global__ __launch_bounds__(256)
void gemm_lm(const unsigned* __restrict__ Aw,   // [M][Kb/2] words
             const unsigned* __restrict__ Bw,   // [N][Kb/2] words
             float* __restrict__ C, int M, int N, int Kb,
             const float* __restrict__ att_s, const float* __restrict__ att_d,
             float* __restrict__ das, float* __restrict__ dad, int hstride) {
    extern __shared__ unsigned smw[];
    const uint32_t sb = smem_u32(smw);
    const int tid  = threadIdx.x;
    const int lane = tid & 31;
    const int wid  = tid >> 5;
    const int g = lane >> 2;
    const int c = lane & 3;
    const int warpM = (wid & 1) * 64;
    const int warpN = (wid >> 1) * 32;
    const int blockM = blockIdx.y * 128;
    const int blockN = blockIdx.x * 128;
    const int KbW = Kb >> 1;
    const int T = Kb >> 6;

    float acc[4][4][4];
    #pragma unroll
    for (int mt = 0; mt < 4; mt++)
        #pragma unroll
        for (int nt = 0; nt < 4; nt++)
            #pragma unroll
            for (int i = 0; i < 4; i++) acc[mt][nt][i] = 0.f;

    // per-lane ldmatrix relative offsets (at ks=0) within a stage
    uint32_t aoff[4], boff[2];
    {
        int mi = lane >> 3, lr = lane & 7;
        #pragma unroll
        for (int mt = 0; mt < 4; mt++) {
            int r = warpM + mt * 16 + (mi & 1) * 8 + lr;
            aoff[mt] = (uint32_t)(r * 128) + ((uint32_t)((mi >> 1) * 16) ^ ((r & 7) << 4));
        }
        #pragma unroll
        for (int p = 0; p < 2; p++) {
            int n = warpN + (2 * p + (mi >> 1)) * 8 + lr;
            boff[p] = 16384u + (uint32_t)(n * 128) + ((uint32_t)((mi & 1) * 16) ^ ((n & 7) << 4));
        }
    }

    auto load_stage = [&](int t, int stg) {
        uint32_t base = sb + stg * STG_BYTES;
        const int k0w = t * 32;
        #pragma unroll
        for (int i = 0; i < 4; i++) {                  // A: 1024 x 16B chunks
            int lin = i * 256 + tid;
            int r = lin >> 3, ch = lin & 7;
            int gRow = blockM + r;
            cpasync16(base + swz(r * 128 + ch * 16),
                      Aw + (size_t)gRow * KbW + k0w + ch * 4,
                      (gRow < M) ? 16 : 0);
        }
        #pragma unroll
        for (int i = 0; i < 4; i++) {                  // B: 1024 x 16B chunks
            int lin = i * 256 + tid;
            int r = lin >> 3, ch = lin & 7;
            cpasync16(base + 16384 + swz(r * 128 + ch * 16),
                      Bw + (size_t)(blockN + r) * KbW + k0w + ch * 4, 16);
        }
    };

    load_stage(0, 0);
    asm volatile("cp.async.commit_group;\n" ::);
    load_stage(1, 1);
    asm volatile("cp.async.commit_group;\n" ::);

    for (int t = 0; t < T; t++) {
        asm volatile("cp.async.wait_group 1;\n" ::);
        __syncthreads();

        if (t + 2 < T) load_stage(t + 2, (t + 2) % 3);
        asm volatile("cp.async.commit_group;\n" ::);

        const uint32_t stgb = sb + (t % 3) * STG_BYTES;

        #pragma unroll
        for (int ks = 0; ks < 4; ks++) {
            unsigned a[4][4], b[2][4];
            #pragma unroll
            for (int mt = 0; mt < 4; mt++)
                ldm4(a[mt], stgb + (aoff[mt] ^ (ks << 5)));
            #pragma unroll
            for (int p = 0; p < 2; p++)
                ldm4(b[p], stgb + (boff[p] ^ (ks << 5)));
            #pragma unroll
            for (int mt = 0; mt < 4; mt++)
                #pragma unroll
                for (int nt = 0; nt < 4; nt++)
                    mma16(acc[mt][nt], a[mt], &b[nt >> 1][(nt & 1) * 2]);
        }
    }

    // ---- fused attention dots: smem cross-warp reduction, plain store ----
    if (att_s) {
        __syncthreads();                       // mainloop done; reuse smem
        float* sred = (float*)smw;             // [128 rows][2]
        sred[tid] = 0.f;
        __syncthreads();
        float asv[8], adv[8];
        #pragma unroll
        for (int nt = 0; nt < 4; nt++) {
            int colg = blockN + warpN + nt * 8 + 2 * c;
            asv[nt * 2]     = att_s[colg];
            asv[nt * 2 + 1] = att_s[colg + 1];
            adv[nt * 2]     = att_d[colg];
            adv[nt * 2 + 1] = att_d[colg + 1];
        }
        #pragma unroll
        for (int mt = 0; mt < 4; mt++) {
            float s0 = 0.f, d0 = 0.f, s1 = 0.f, d1 = 0.f;
            #pragma unroll
            for (int nt = 0; nt < 4; nt++) {
                s0 += acc[mt][nt][0] * asv[nt * 2] + acc[mt][nt][1] * asv[nt * 2 + 1];
                d0 += acc[mt][nt][0] * adv[nt * 2] + acc[mt][nt][1] * adv[nt * 2 + 1];
                s1 += acc[mt][nt][2] * asv[nt * 2] + acc[mt][nt][3] * asv[nt * 2 + 1];
                d1 += acc[mt][nt][2] * adv[nt * 2] + acc[mt][nt][3] * adv[nt * 2 + 1];
            }
            #pragma unroll
            for (int o = 1; o <= 2; o <<= 1) {
                s0 += __shfl_xor_sync(0xffffffffu, s0, o);
                d0 += __shfl_xor_sync(0xffffffffu, d0, o);
                s1 += __shfl_xor_sync(0xffffffffu, s1, o);
                d1 += __shfl_xor_sync(0xffffffffu, d1, o);
            }
            if (c == 0) {
                int r0 = warpM + mt * 16 + g;
                atomicAdd(&sred[r0 * 2],           s0);
                atomicAdd(&sred[r0 * 2 + 1],       d0);
                atomicAdd(&sred[(r0 + 8) * 2],     s1);
                atomicAdd(&sred[(r0 + 8) * 2 + 1], d1);
            }
        }
        __syncthreads();
        if (tid < 128) {
            int row = blockM + tid;
            if (row < M) {
                das[row * hstride + blockIdx.x] = sred[tid * 2];
                dad[row * hstride + blockIdx.x] = sred[tid * 2 + 1];
            }
        }
    }

    // ---- store C ----
    #pragma unroll
    for (int mt = 0; mt < 4; mt++)
        #pragma unroll
        for (int nt = 0; nt < 4; nt++) {
            int row0 = blockM + warpM + mt * 16 + g;
            int col  = blockN + warpN + nt * 8 + 2 * c;
            if (row0 < M)
                *(float2*)(C + (size_t)row0 * N + col) =
                    make_float2(acc[mt][nt][0], acc[mt][nt][1]);
            int row1 = row0 + 8;
            if (row1 < M)
                *(float2*)(C + (size_t)row1 * N + col) =
                    make_float2(acc[mt][nt][2], acc[mt][nt][3]);
        }
}

// ---------------- GAT aggregation (CSR per-dst-node, local softmax) --------
__device__ __forceinline__ void sAtomicMaxF(float* a, float v) {
    int* ai = (int*)a;
    int old = *ai;
    while (__int_as_float(old) < v) {
        int assumed = old;
        old = atomicCAS(ai, assumed, __float_as_int(v));
        if (old == assumed) break;
    }
}

__global__ __launch_bounds__(256)
void k_agg1(const float* __restrict__ bias) {
    int n = blockIdx.x;
    int s0 = d_off[n];
    int deg = d_off[n + 1] - s0;
    __shared__ float sm[H1H], sz[H1H], sad[H1H];
    int tid = threadIdx.x;
    if (tid < H1H) { sad[tid] = d_ad1[n * H1H + tid]; sm[tid] = -1e30f; sz[tid] = 0.f; }
    __syncthreads();
    for (int idx = tid; idx < deg * H1H; idx += 256) {
        int e = idx >> 3, hh = idx & 7;
        int src = d_csr[s0 + e];
        float v = d_as1[src * H1H + hh] + sad[hh];
        v = v > 0.f ? v : NEG * v;
        sAtomicMaxF(&sm[hh], v);
    }
    __syncthreads();
    for (int idx = tid; idx < deg * H1H; idx += 256) {
        int e = idx >> 3, hh = idx & 7;
        int src = d_csr[s0 + e];
        float v = d_as1[src * H1H + hh] + sad[hh];
        v = v > 0.f ? v : NEG * v;
        atomicAdd(&sz[hh], __expf(v - sm[hh]));
    }
    __syncthreads();
    int c0 = tid * 4;
    int hh = c0 >> 7;
    float m = sm[hh], invz = 1.f / sz[hh], ad = sad[hh];
    float4 acc = make_float4(0.f, 0.f, 0.f, 0.f);
    for (int e = 0; e < deg; e++) {
        int src = d_csr[s0 + e];
        float v = d_as1[src * H1H + hh] + ad;
        v = v > 0.f ? v : NEG * v;
        float al = __expf(v - m) * invz;
        float4 hv = *(const float4*)(d_h1 + (size_t)src * F1 + c0);
        acc.x += al * hv.x; acc.y += al * hv.y;
        acc.z += al * hv.z; acc.w += al * hv.w;
    }
    float4 bb = *(const float4*)(bias + c0);
    acc.x += bb.x; acc.y += bb.y; acc.z += bb.z; acc.w += bb.w;
    *(float4*)(d_g1 + (size_t)n * F1 + c0) = acc;
}

__global__ __launch_bounds__(128)
void k_agg2(const float* __restrict__ bias) {
    int n = blockIdx.x;
    int s0 = d_off[n];
    int deg = d_off[n + 1] - s0;
    __shared__ float sm, sz, sad;
    int tid = threadIdx.x;
    if (tid == 0) { sad = d_ad2[n]; sm = -1e30f; sz = 0.f; }
    __syncthreads();
    for (int e = tid; e < deg; e += 128) {
        float v = d_as2[d_csr[s0 + e]] + sad;
        v = v > 0.f ? v : NEG * v;
        sAtomicMaxF(&sm, v);
    }
    __syncthreads();
    for (int e = tid; e < deg; e += 128) {
        float v = d_as2[d_csr[s0 + e]] + sad;
        v = v > 0.f ? v : NEG * v;
        atomicAdd(&sz, __expf(v - sm));
    }
    __syncthreads();
    float m = sm, invz = 1.f / sz, ad = sad;
    float acc = 0.f;
    for (int e = 0; e < deg; e++) {
        int src = d_csr[s0 + e];
        float v = d_as2[src] + ad;
        v = v > 0.f ? v : NEG * v;
        acc += __expf(v - m) * invz * d_h2[(size_t)src * F2 + tid];
    }
    d_g2[(size_t)n * F2 + tid] = acc + bias[tid];
}

// ---------------- BatchNorm ------------------------------------------------
__global__ void bn_stats(const float* __restrict__ x, float* __restrict__ sum,
                         float* __restrict__ sq, int F) {
    int col = blockIdx.x * 128 + threadIdx.x;
    float s = 0.f, q = 0.f;
    for (int r = blockIdx.y; r < NN; r += gridDim.y) {
        float v = x[(size_t)r * F + col];
        s += v; q += v * v;
    }
    atomicAdd(&sum[col], s);
    atomicAdd(&sq[col], q);
}

__global__ void bn_final(const float* __restrict__ sum, const float* __restrict__ sq,
                         const float* __restrict__ gamma, const float* __restrict__ beta,
                         float* __restrict__ scale, float* __restrict__ shift, int F) {
    int c = blockIdx.x * blockDim.x + threadIdx.x;
    if (c < F) {
        float mu  = sum[c] * (1.f / NN);
        float var = sq[c] * (1.f / NN) - mu * mu;
        float sc  = gamma[c] * rsqrtf(var + BNEPS);
        scale[c] = sc;
        shift[c] = beta[c] - mu * sc;
    }
}

// ---------------- classifier head (fused BN2+ELU) ---------------------------
__global__ __launch_bounds__(64)
void k_classifier(const float* __restrict__ g2, const float* __restrict__ scale,
                  const float* __restrict__ shift,
                  const float* __restrict__ Wc1, const float* __restrict__ bc1,
                  const float* __restrict__ Wc2, const float* __restrict__ bc2,
                  float* __restrict__ out) {
    int n = blockIdx.x;
    int tid = threadIdx.x;
    __shared__ float sx[128], sh[64];
    float v0 = g2[(size_t)n * F2 + tid]      * scale[tid]      + shift[tid];
    float v1 = g2[(size_t)n * F2 + 64 + tid] * scale[tid + 64] + shift[tid + 64];
    sx[tid]      = eluf(v0);
    sx[tid + 64] = eluf(v1);
    __syncthreads();
    float s = bc1[tid];
    #pragma unroll 8
    for (int k = 0; k < 128; k++) s += sx[k] * Wc1[k * 64 + tid];
    sh[tid] = fmaxf(s, 0.f);
    __syncthreads();
    if (tid < 2) {
        float o = bc2[tid];
        #pragma unroll 8
        for (int k = 0; k < 64; k++) o += sh[k] * Wc2[k * 2 + tid];
        out[n * 2 + tid] = o;
    }
}

// ---------------- launch ----------------------------------------------------
extern "C" void kernel_launch(void* const* d_in, const int* in_sizes, int n_in,
                              void* d_out, int out_size) {
    const float* x     = (const float*)d_in[0];
    const void*  ei    = d_in[1];
    const float* W1    = (const float*)d_in[2];
    const float* atts1 = (const float*)d_in[3];
    const float* attd1 = (const float*)d_in[4];
    const float* b1    = (const float*)d_in[5];
    const float* W2    = (const float*)d_in[6];
    const float* atts2 = (const float*)d_in[7];
    const float* attd2 = (const float*)d_in[8];
    const float* b2    = (const float*)d_in[9];
    const float* g1    = (const float*)d_in[10];
    const float* be1   = (const float*)d_in[11];
    const float* g2w   = (const float*)d_in[12];
    const float* be2   = (const float*)d_in[13];
    const float* Wc1   = (const float*)d_in[14];
    const float* bc1   = (const float*)d_in[15];
    const float* Wc2   = (const float*)d_in[16];
    const float* bc2   = (const float*)d_in[17];
    float*       out   = (float*)d_out;

    void *p_deg, *p_h1, *p_g2, *p_bsum, *p_bsq, *p_scale, *p_shift;
    void *p_as1, *p_ad1, *p_as2, *p_ad2, *p_h2, *p_g1;
    void *p_xs, *p_g1s, *p_w1t, *p_w2t;
    cudaGetSymbolAddress(&p_deg,   d_deg);
    cudaGetSymbolAddress(&p_h1,    d_h1);
    cudaGetSymbolAddress(&p_g1,    d_g1);
    cudaGetSymbolAddress(&p_h2,    d_h2);
    cudaGetSymbolAddress(&p_g2,    d_g2);
    cudaGetSymbolAddress(&p_bsum,  d_bsum);
    cudaGetSymbolAddress(&p_bsq,   d_bsq);
    cudaGetSymbolAddress(&p_scale, d_scale);
    cudaGetSymbolAddress(&p_shift, d_shift);
    cudaGetSymbolAddress(&p_as1,   d_as1);
    cudaGetSymbolAddress(&p_ad1,   d_ad1);
    cudaGetSymbolAddress(&p_as2,   d_as2);
    cudaGetSymbolAddress(&p_ad2,   d_ad2);
    cudaGetSymbolAddress(&p_xs,    d_xs);
    cudaGetSymbolAddress(&p_g1s,   d_g1s);
    cudaGetSymbolAddress(&p_w1t,   d_w1t);
    cudaGetSymbolAddress(&p_w2t,   d_w2t);

    cudaFuncSetAttribute(gemm_lm, cudaFuncAttributeMaxDynamicSharedMemorySize,
                         GEMM_SMEM);

    // conversions + CSR build (gemm1 is launch #5 incl. memset for ncu -s 5)
    conv_x<<<(NN * (DIN / 2) + 255) / 256, 256>>>(x);                      // 1
    conv_wt<<<(F1 * (K1P / 2) + 255) / 256, 256>>>(W1, (unsigned*)p_w1t, DIN, F1); // 2
    conv_wt<<<(F2 * (K2P / 2) + 255) / 256, 256>>>(W2, (unsigned*)p_w2t, F1, F2);  // 3
    cudaMemsetAsync(p_deg, 0, NN * sizeof(int));                            // 4

    // ---- GAT layer 1: split-bf16 HMMA GEMM (fused attention dots) ----
    {
        dim3 grid(F1 / 128, (NN + 127) / 128);
        gemm_lm<<<grid, 256, GEMM_SMEM>>>((const unsigned*)p_xs,            // 5
                                          (const unsigned*)p_w1t,
                                          (float*)p_h1, NN, F1, K1P,
                                          atts1, attd1,
                                          (float*)p_as1, (float*)p_ad1, H1H);
    }

    k_detect<<<1, 64>>>(ei);
    k_count<<<(ETOT + 255) / 256, 256>>>(ei);
    k_scan<<<1, 1024>>>();
    k_scatter<<<(ETOT + 255) / 256, 256>>>(ei);   // also zeroes BN1 accumulators

    k_agg1<<<NN, 256>>>(b1);

    // BN1 stats -> conv_g1 applies BN+ELU, writes split A', zeroes BN2 accs
    {
        dim3 grid(F1 / 128, 128);
        bn_stats<<<grid, 128>>>((const float*)p_g1, (float*)p_bsum, (float*)p_bsq, F1);
    }
    bn_final<<<F1 / 128, 128>>>((const float*)p_bsum, (const float*)p_bsq, g1, be1,
                                (float*)p_scale, (float*)p_shift, F1);
    conv_g1<<<(NN * (F1 / 2) + 255) / 256, 256>>>((const float*)p_scale,
                                                  (const float*)p_shift);

    // ---- GAT layer 2: split-bf16 HMMA GEMM (fused attention dots) ----
    {
        dim3 grid(1, (NN + 127) / 128);
        gemm_lm<<<grid, 256, GEMM_SMEM>>>((const unsigned*)p_g1s,
                                          (const unsigned*)p_w2t,
                                          (float*)p_h2, NN, F2, K2P,
                                          atts2, attd2,
                                          (float*)p_as2, (float*)p_ad2, 1);
    }
    k_agg2<<<NN, 128>>>(b2);

    // BN2 stats (apply fused into classifier)
    {
        dim3 grid(F2 / 128, 128);
        bn_stats<<<grid, 128>>>((const float*)p_g2, (float*)p_bsum, (float*)p_bsq, F2);
    }
    bn_final<<<1, 128>>>((const float*)p_bsum, (const float*)p_bsq, g2w, be2,
                         (float*)p_scale, (float*)p_shift, F2);

    // ---- classifier head (fused BN2+ELU) ----
    k_classifier<<<NN, 64>>>((const float*)p_g2, (const float*)p_scale,
                             (const float*)p_shift, Wc1, bc1, Wc2, bc2, out);
}